// round 10
// baseline (speedup 1.0000x reference)
#include <cuda_runtime.h>
#include <cstdint>
#include <math.h>

// ---------------- problem constants ----------------
#define N_NODES 27648
#define F_IN    256
#define HC      512
#define NHEAD   4
#define CDIM    128
#define DE      16
#define HID     256
#define NA      48
#define NOUT    576
#define CAP     64
#define SLOPE_ATT 0.2f
#define SLOPE     0.01f
#define EPB     512
#define NBLK    592            // 4 blocks/SM x 148 SMs, all resident
#define NTHR    256

// ---------------- device scratch ----------------
__device__ float g_wv[F_IN * 8];                // wv[f][j]: j<4 src head, j>=4 dst head
__device__ float g_wattE[DE * NHEAD];
__device__ float g_easum[DE];
__device__ int   g_dstcnt[NOUT];                // zero at launch start; reset by Phase B
__device__ int   g_ebsrc[NOUT * CAP];           // src node ids
__device__ int   g_ebeid[NOUT * CAP];           // edge ids
__device__ float g_xagg[NOUT * NHEAD * F_IN];   // per-dst per-head aggregated x
__device__ float g_hact[NOUT * HC];
__device__ int   g_barcnt;
__device__ volatile int g_sense;

__device__ __forceinline__ int diag_node(int i) { return (i / NA) * (NA * NA) + (i % NA) * (NA + 1); }

// global barrier: sense-reversing, self-resetting (replay-deterministic)
__device__ __forceinline__ void gbar(int* ls) {
    __syncthreads();
    if (threadIdx.x == 0) {
        int s = (*ls ^= 1);
        __threadfence();
        if (atomicAdd(&g_barcnt, 1) == NBLK - 1) {
            g_barcnt = 0;
            __threadfence();
            g_sense = s;
        } else {
            while (g_sense != s) { __nanosleep(32); }
        }
        __threadfence();
    }
    __syncthreads();
}

// Phase B smem overlay (an first: 16B aligned for float4 stores)
struct BSm {
    float an[(CAP + 1) * 8];
    float w[(CAP + 1) * NHEAD];
    float wE[DE * NHEAD];
    float aloop[NHEAD];
    float inv[NHEAD];
    int   sn[CAP + 1];
    int   eid[CAP];
    int   cnt;
};

#define SMEM_BYTES 16896    // Phase D hs[8][512] = 16KB is the max user

__global__ void __launch_bounds__(NTHR, 4)
k_mega(const float* __restrict__ x, const int* __restrict__ ei, const float* __restrict__ ea,
       const float* __restrict__ W, const float* __restrict__ att_src, const float* __restrict__ att_dst,
       const float* __restrict__ W_edge, const float* __restrict__ att_edge,
       const float* __restrict__ bias, const float* __restrict__ fcW, const float* __restrict__ fcb,
       float* __restrict__ out, int E, float invE)
{
    extern __shared__ __align__(128) char sm[];
    __shared__ int ls;
    __shared__ float s_ea[DE];
    const int tid = threadIdx.x;
    const int wid = tid >> 5, lane = tid & 31;
    if (tid == 0) ls = g_sense;

    // ================= Phase A: wv + wattE + easum + scan/bucket =============
    // wv: blocks 320..575 (one warp per (f,j) pair); wattE: blocks 576..583.
    if (blockIdx.x >= 320 && blockIdx.x < 576) {
        int pair = (blockIdx.x - 320) * 8 + wid;  // < 2048
        int f = pair >> 3, j = pair & 7, h = j & 3;
        const float* att = ((j < 4) ? att_src : att_dst) + h * CDIM;
        float4 w4 = *(const float4*)(W + (size_t)f * HC + h * CDIM + lane * 4);
        float4 a4 = *(const float4*)(att + lane * 4);
        float s = w4.x * a4.x + w4.y * a4.y + w4.z * a4.z + w4.w * a4.w;
        #pragma unroll
        for (int off = 16; off > 0; off >>= 1) s += __shfl_down_sync(0xffffffffu, s, off);
        if (lane == 0) g_wv[f * 8 + j] = s;
    } else if (blockIdx.x >= 576 && blockIdx.x < 584) {
        int pair = (blockIdx.x - 576) * 8 + wid;  // < 64
        int d = pair >> 2, h = pair & 3;
        float4 w4 = *(const float4*)(W_edge + (size_t)d * HC + h * CDIM + lane * 4);
        float4 a4 = *(const float4*)(att_edge + h * CDIM + lane * 4);
        float s = w4.x * a4.x + w4.y * a4.y + w4.z * a4.z + w4.w * a4.w;
        #pragma unroll
        for (int off = 16; off > 0; off >>= 1) s += __shfl_down_sync(0xffffffffu, s, off);
        if (lane == 0) g_wattE[pair] = s;
    }
    // scan+easum: all blocks, grid-stride over slabs
    {
        if (tid < DE) s_ea[tid] = 0.f;
        __syncthreads();
        const int nslab = (E + EPB - 1) / EPB;
        const int lim4 = E * 4;
        float4 acc = make_float4(0.f, 0.f, 0.f, 0.f);
        for (int slab = blockIdx.x; slab < nslab; slab += NBLK) {
            const int ebase = slab * EPB;
            // dense edge_attr accumulation
            const float4* ea4 = (const float4*)ea;
            const int g0 = ebase * 4;
            #pragma unroll
            for (int i = 0; i < EPB * 4 / NTHR; i++) {
                int g4 = g0 + tid + i * NTHR;
                if (g4 < lim4) {
                    float4 v = ea4[g4];
                    acc.x += v.x; acc.y += v.y; acc.z += v.z; acc.w += v.w;
                }
            }
            // scan dst + append (src, eid) to buckets
            if (tid < EPB / 4) {
                const int* dst = ei + E;
                int4 d4 = *(const int4*)(dst + ebase + tid * 4);
                #pragma unroll
                for (int j = 0; j < 4; j++) {
                    int d = (j == 0) ? d4.x : (j == 1) ? d4.y : (j == 2) ? d4.z : d4.w;
                    int e = ebase + tid * 4 + j;
                    int rem = d % (NA * NA);
                    if (e < E && rem % (NA + 1) == 0) {
                        int dc = (d / (NA * NA)) * NA + rem / (NA + 1);
                        int p = atomicAdd(&g_dstcnt[dc], 1);
                        if (p < CAP) {
                            g_ebsrc[dc * CAP + p] = ei[e];
                            g_ebeid[dc * CAP + p] = e;
                        }
                    }
                }
            }
        }
        int d0 = (tid & 3) * 4;
        atomicAdd(&s_ea[d0 + 0], acc.x);
        atomicAdd(&s_ea[d0 + 1], acc.y);
        atomicAdd(&s_ea[d0 + 2], acc.z);
        atomicAdd(&s_ea[d0 + 3], acc.w);
        __syncthreads();
        if (tid < DE) atomicAdd(&g_easum[tid], s_ea[tid]);
    }
    gbar(&ls);   // 1

    // ================= Phase B: per-dst scores + softmax + x-aggregation =====
    if (blockIdx.x < NOUT) {
        const int dc = blockIdx.x;
        BSm* bs = (BSm*)sm;
        if (tid < DE * NHEAD) bs->wE[tid] = g_wattE[tid];
        if (tid == 0) {
            int c = g_dstcnt[dc];
            bs->cnt = c < CAP ? c : CAP;
            g_dstcnt[dc] = 0;                       // restore for next replay
        }
        __syncthreads();
        if (tid < NHEAD) {
            float a = 0.f;
            #pragma unroll
            for (int d = 0; d < DE; d++) a += g_easum[d] * invE * bs->wE[d * NHEAD + tid];
            bs->aloop[tid] = a;
        }
        const int cnt = bs->cnt;
        const int dn = diag_node(dc);
        if (tid < cnt) {
            bs->sn[tid] = g_ebsrc[dc * CAP + tid];
            bs->eid[tid] = g_ebeid[dc * CAP + tid];
        } else if (tid == cnt) {
            bs->sn[cnt] = dn;                       // self-loop source = dst node
        }
        __syncthreads();
        // sweep1: per-entry 8 attention dots (warp per entry)
        for (int ent = wid; ent <= cnt; ent += 8) {
            const float4* xr4 = (const float4*)(x + (size_t)bs->sn[ent] * F_IN);
            float4 a4 = xr4[lane * 2];
            float4 b4 = xr4[lane * 2 + 1];
            float xv[8] = {a4.x, a4.y, a4.z, a4.w, b4.x, b4.y, b4.z, b4.w};
            float p[8] = {0.f, 0.f, 0.f, 0.f, 0.f, 0.f, 0.f, 0.f};
            #pragma unroll
            for (int q = 0; q < 8; q++) {
                const float4* wv4 = (const float4*)&g_wv[(lane * 8 + q) * 8];
                float4 w0 = wv4[0], w1 = wv4[1];
                p[0] += xv[q] * w0.x; p[1] += xv[q] * w0.y;
                p[2] += xv[q] * w0.z; p[3] += xv[q] * w0.w;
                p[4] += xv[q] * w1.x; p[5] += xv[q] * w1.y;
                p[6] += xv[q] * w1.z; p[7] += xv[q] * w1.w;
            }
            #pragma unroll
            for (int j = 0; j < 8; j++) {
                float s = p[j];
                #pragma unroll
                for (int off = 16; off > 0; off >>= 1) s += __shfl_down_sync(0xffffffffu, s, off);
                p[j] = s;
            }
            if (lane == 0) {
                *(float4*)&bs->an[ent * 8]     = make_float4(p[0], p[1], p[2], p[3]);
                *(float4*)&bs->an[ent * 8 + 4] = make_float4(p[4], p[5], p[6], p[7]);
            }
        }
        __syncthreads();
        // logits (+ea-logit recompute from L2-hot ea) -> leaky
        if (tid < cnt) {
            const float4* r = (const float4*)(ea + (size_t)bs->eid[tid] * DE);
            float l0 = 0.f, l1 = 0.f, l2 = 0.f, l3 = 0.f;
            #pragma unroll
            for (int q = 0; q < 4; q++) {
                float4 v = r[q];
                const float* w = &bs->wE[q * 4 * NHEAD];
                l0 += v.x * w[0] + v.y * w[4] + v.z * w[8]  + v.w * w[12];
                l1 += v.x * w[1] + v.y * w[5] + v.z * w[9]  + v.w * w[13];
                l2 += v.x * w[2] + v.y * w[6] + v.z * w[10] + v.w * w[14];
                l3 += v.x * w[3] + v.y * w[7] + v.z * w[11] + v.w * w[15];
            }
            float le[4] = {l0, l1, l2, l3};
            #pragma unroll
            for (int h = 0; h < NHEAD; h++) {
                float l = bs->an[tid * 8 + h] + bs->an[cnt * 8 + 4 + h] + le[h];
                bs->w[tid * 4 + h] = (l > 0.f) ? l : SLOPE_ATT * l;
            }
        } else if (tid == cnt) {
            #pragma unroll
            for (int h = 0; h < NHEAD; h++) {
                float l = bs->an[cnt * 8 + h] + bs->an[cnt * 8 + 4 + h] + bs->aloop[h];
                bs->w[cnt * 4 + h] = (l > 0.f) ? l : SLOPE_ATT * l;
            }
        }
        __syncthreads();
        const int total = cnt + 1;
        if (tid < NHEAD) {
            float m = -3.0e38f;
            for (int e = 0; e < total; e++) m = fmaxf(m, bs->w[e * 4 + tid]);
            float su = 0.f;
            for (int e = 0; e < total; e++) { float w = __expf(bs->w[e * 4 + tid] - m); bs->w[e * 4 + tid] = w; su += w; }
            bs->inv[tid] = 1.f / (su + 1e-16f);
        }
        __syncthreads();
        // sweep2: x-space aggregation (x rows L1/L2-hot from sweep1)
        float acc0 = 0.f, acc1 = 0.f, acc2 = 0.f, acc3 = 0.f;
        for (int e = 0; e < total; e++) {
            float xv = x[(size_t)bs->sn[e] * F_IN + tid];
            acc0 += bs->w[e * 4 + 0] * xv;
            acc1 += bs->w[e * 4 + 1] * xv;
            acc2 += bs->w[e * 4 + 2] * xv;
            acc3 += bs->w[e * 4 + 3] * xv;
        }
        float* xo = &g_xagg[(size_t)dc * NHEAD * F_IN];
        xo[0 * F_IN + tid] = acc0 * bs->inv[0];
        xo[1 * F_IN + tid] = acc1 * bs->inv[1];
        xo[2 * F_IN + tid] = acc2 * bs->inv[2];
        xo[3 * F_IN + tid] = acc3 * bs->inv[3];
    }
    gbar(&ls);   // 2

    // ================= Phase C: hact = leaky(xagg @ W + bias) ================
    if (blockIdx.x == 590 && tid < DE) g_easum[tid] = 0.f;   // restore for replay
    if (blockIdx.x < (NOUT / 8) * 4) {
        const int g = blockIdx.x >> 2, cg = blockIdx.x & 3;   // 8 rows x 128 cols (= head cg)
        float* xa = (float*)sm;                               // [8][256]
        for (int i = tid; i < 8 * F_IN; i += NTHR)
            xa[i] = g_xagg[(size_t)(g * 8 + (i >> 8)) * NHEAD * F_IN + cg * F_IN + (i & (F_IN - 1))];
        __syncthreads();
        const int r = wid;                                    // warp = row
        const int n = cg * 128 + lane * 4;
        float4 acc = make_float4(0.f, 0.f, 0.f, 0.f);
        #pragma unroll 4
        for (int k = 0; k < F_IN; k++) {
            float xv = xa[r * F_IN + k];                      // broadcast LDS
            float4 w4 = *(const float4*)(W + (size_t)k * HC + n);
            acc.x += xv * w4.x; acc.y += xv * w4.y;
            acc.z += xv * w4.z; acc.w += xv * w4.w;
        }
        float4 b4 = *(const float4*)(bias + n);
        acc.x += b4.x; acc.y += b4.y; acc.z += b4.z; acc.w += b4.w;
        acc.x = (acc.x > 0.f) ? acc.x : SLOPE * acc.x;
        acc.y = (acc.y > 0.f) ? acc.y : SLOPE * acc.y;
        acc.z = (acc.z > 0.f) ? acc.z : SLOPE * acc.z;
        acc.w = (acc.w > 0.f) ? acc.w : SLOPE * acc.w;
        *(float4*)&g_hact[(size_t)(g * 8 + r) * HC + n] = acc;
    }
    gbar(&ls);   // 3

    // ================= Phase D: out = leaky(hact @ fcW + fcb) ================
    if (blockIdx.x < (NOUT / 8) * 2) {
        const int g = blockIdx.x >> 1, og = blockIdx.x & 1;   // 8 rows x 128 cols
        float* hs = (float*)sm;                               // [8][512]
        for (int i = tid; i < 8 * HC; i += NTHR)
            hs[i] = g_hact[(size_t)(g * 8 + (i >> 9)) * HC + (i & (HC - 1))];
        __syncthreads();
        const int r = wid;
        const int n = og * 128 + lane * 4;
        float4 acc = make_float4(0.f, 0.f, 0.f, 0.f);
        #pragma unroll 4
        for (int k = 0; k < HC; k++) {
            float hv = hs[r * HC + k];                        // broadcast LDS
            float4 f4 = *(const float4*)(fcW + (size_t)k * HID + n);
            acc.x += hv * f4.x; acc.y += hv * f4.y;
            acc.z += hv * f4.z; acc.w += hv * f4.w;
        }
        float4 b4 = *(const float4*)(fcb + n);
        acc.x += b4.x; acc.y += b4.y; acc.z += b4.z; acc.w += b4.w;
        acc.x = (acc.x > 0.f) ? acc.x : SLOPE * acc.x;
        acc.y = (acc.y > 0.f) ? acc.y : SLOPE * acc.y;
        acc.z = (acc.z > 0.f) ? acc.z : SLOPE * acc.z;
        acc.w = (acc.w > 0.f) ? acc.w : SLOPE * acc.w;
        *(float4*)&out[(size_t)(g * 8 + r) * HID + n] = acc;
    }
}

// ---------------- launch ----------------
extern "C" void kernel_launch(void* const* d_in, const int* in_sizes, int n_in,
                              void* d_out, int out_size) {
    const float* x        = (const float*)d_in[0];
    const int*   ei       = (const int*)d_in[1];
    const float* ea       = (const float*)d_in[2];
    const float* W        = (const float*)d_in[5];
    const float* att_src  = (const float*)d_in[6];
    const float* att_dst  = (const float*)d_in[7];
    const float* W_edge   = (const float*)d_in[8];
    const float* att_edge = (const float*)d_in[9];
    const float* bias     = (const float*)d_in[10];
    const float* fcW      = (const float*)d_in[11];
    const float* fcb      = (const float*)d_in[12];
    float* out = (float*)d_out;
    const int E = in_sizes[1] / 2;

    k_mega<<<NBLK, NTHR, SMEM_BYTES>>>(x, ei, ea, W, att_src, att_dst, W_edge, att_edge,
                                       bias, fcW, fcb, out, E, 1.0f / (float)E);
}

// round 12
// speedup vs baseline: 1.0063x; 1.0063x over previous
#include <cuda_runtime.h>
#include <cstdint>
#include <math.h>

// ---------------- problem constants ----------------
#define N_NODES 27648
#define F_IN    256
#define HC      512
#define NHEAD   4
#define CDIM    128
#define DE      16
#define HID     256
#define NA      48
#define NOUT    576
#define CAP     64
#define SLOPE_ATT 0.2f
#define SLOPE     0.01f
#define EPB     512

// ---------------- device scratch ----------------
__device__ float g_wv[F_IN * 8];                // wv[f][j]: j<4 src head, j>=4 dst head
__device__ float g_wattE[DE * NHEAD];
__device__ float g_easum[DE];                   // zero-init; reset by k_gat each replay
__device__ int   g_dstcnt[NOUT];                // zero-init; reset by k_dst each replay
__device__ int   g_ebsrc[NOUT * CAP];           // src node ids
__device__ int   g_ebeid[NOUT * CAP];           // edge ids
__device__ float g_xagg[NOUT * NHEAD * F_IN];   // per-dst per-head aggregated x
__device__ float g_hact[NOUT * HC];

__device__ __forceinline__ int diag_node(int i) { return (i / NA) * (NA * NA) + (i % NA) * (NA + 1); }

// ================= K1: prep — wv + wattE + easum + scan/bucket ==============
// grid = nslab + 264. blocks [0,nslab): one slab each; [nslab,nslab+256): wv;
// [nslab+256, nslab+264): wattE.
__global__ void __launch_bounds__(256)
k_prep(const int* __restrict__ ei, const float* __restrict__ ea,
       const float* __restrict__ W, const float* __restrict__ att_src,
       const float* __restrict__ att_dst, const float* __restrict__ W_edge,
       const float* __restrict__ att_edge, int E, int nslab)
{
    const int tid = threadIdx.x;
    const int wid = tid >> 5, lane = tid & 31;
    const int bid = blockIdx.x;

    if (bid < nslab) {
        __shared__ float s_ea[DE];
        if (tid < DE) s_ea[tid] = 0.f;
        __syncthreads();
        const int ebase = bid * EPB;
        // dense edge_attr accumulation (slab = 512 edges x 16 dims = 2048 float4)
        {
            const float4* ea4 = (const float4*)ea;
            const int g0 = ebase * 4;
            const int lim4 = E * 4;
            float4 acc = make_float4(0.f, 0.f, 0.f, 0.f);
            #pragma unroll
            for (int i = 0; i < EPB * 4 / 256; i++) {
                int g4 = g0 + tid + i * 256;
                if (g4 < lim4) {
                    float4 v = ea4[g4];
                    acc.x += v.x; acc.y += v.y; acc.z += v.z; acc.w += v.w;
                }
            }
            int d0 = (tid & 3) * 4;
            atomicAdd(&s_ea[d0 + 0], acc.x);
            atomicAdd(&s_ea[d0 + 1], acc.y);
            atomicAdd(&s_ea[d0 + 2], acc.z);
            atomicAdd(&s_ea[d0 + 3], acc.w);
        }
        // scan dst slab, append (src, eid) to per-dst buckets
        if (tid < EPB / 4) {
            const int* dst = ei + E;
            const int e0 = ebase + tid * 4;
            if (e0 + 3 < E) {
                int4 d4 = *(const int4*)(dst + e0);
                #pragma unroll
                for (int j = 0; j < 4; j++) {
                    int d = (j == 0) ? d4.x : (j == 1) ? d4.y : (j == 2) ? d4.z : d4.w;
                    int rem = d % (NA * NA);
                    if (rem % (NA + 1) == 0) {
                        int e = e0 + j;
                        int dc = (d / (NA * NA)) * NA + rem / (NA + 1);
                        int p = atomicAdd(&g_dstcnt[dc], 1);
                        if (p < CAP) {
                            g_ebsrc[dc * CAP + p] = ei[e];
                            g_ebeid[dc * CAP + p] = e;
                        }
                    }
                }
            } else {
                for (int j = 0; j < 4; j++) {
                    int e = e0 + j;
                    if (e >= E) break;
                    int d = dst[e];
                    int rem = d % (NA * NA);
                    if (rem % (NA + 1) == 0) {
                        int dc = (d / (NA * NA)) * NA + rem / (NA + 1);
                        int p = atomicAdd(&g_dstcnt[dc], 1);
                        if (p < CAP) {
                            g_ebsrc[dc * CAP + p] = ei[e];
                            g_ebeid[dc * CAP + p] = e;
                        }
                    }
                }
            }
        }
        __syncthreads();
        if (tid < DE) atomicAdd(&g_easum[tid], s_ea[tid]);
    } else if (bid < nslab + 256) {
        // wv[f][j] = sum_c W[f, h*128+c] * att_{src|dst}[h, c]; warp per (f,j)
        int pair = (bid - nslab) * 8 + wid;       // < 2048
        int f = pair >> 3, j = pair & 7, h = j & 3;
        const float* att = ((j < 4) ? att_src : att_dst) + h * CDIM;
        float4 w4 = *(const float4*)(W + (size_t)f * HC + h * CDIM + lane * 4);
        float4 a4 = *(const float4*)(att + lane * 4);
        float s = w4.x * a4.x + w4.y * a4.y + w4.z * a4.z + w4.w * a4.w;
        #pragma unroll
        for (int off = 16; off > 0; off >>= 1) s += __shfl_down_sync(0xffffffffu, s, off);
        if (lane == 0) g_wv[f * 8 + j] = s;
    } else {
        int pair = (bid - nslab - 256) * 8 + wid; // < 64
        int d = pair >> 2, h = pair & 3;
        float4 w4 = *(const float4*)(W_edge + (size_t)d * HC + h * CDIM + lane * 4);
        float4 a4 = *(const float4*)(att_edge + h * CDIM + lane * 4);
        float s = w4.x * a4.x + w4.y * a4.y + w4.z * a4.z + w4.w * a4.w;
        #pragma unroll
        for (int off = 16; off > 0; off >>= 1) s += __shfl_down_sync(0xffffffffu, s, off);
        if (lane == 0) g_wattE[pair] = s;
    }
}

// ================= K2: per-dst scores + softmax + x-aggregation =============
__global__ void __launch_bounds__(256)
k_dst(const float* __restrict__ x, const float* __restrict__ ea, float invE)
{
    const int dc = blockIdx.x;
    const int tid = threadIdx.x;
    const int wid = tid >> 5, lane = tid & 31;
    __shared__ float s_an[(CAP + 1) * 8];
    __shared__ float s_w[(CAP + 1) * NHEAD];
    __shared__ float s_wE[DE * NHEAD];
    __shared__ float s_aloop[NHEAD];
    __shared__ float s_inv[NHEAD];
    __shared__ int   s_sn[CAP + 1];
    __shared__ int   s_eid[CAP];
    __shared__ int   s_cnt;

    if (tid < DE * NHEAD) s_wE[tid] = g_wattE[tid];
    if (tid == 0) {
        int c = g_dstcnt[dc];
        s_cnt = c < CAP ? c : CAP;
        g_dstcnt[dc] = 0;                          // restore for next replay
    }
    __syncthreads();
    if (tid < NHEAD) {
        float a = 0.f;
        #pragma unroll
        for (int d = 0; d < DE; d++) a += g_easum[d] * invE * s_wE[d * NHEAD + tid];
        s_aloop[tid] = a;
    }
    const int cnt = s_cnt;
    const int dn = diag_node(dc);
    if (tid < cnt) {
        s_sn[tid] = g_ebsrc[dc * CAP + tid];
        s_eid[tid] = g_ebeid[dc * CAP + tid];
    } else if (tid == cnt) {
        s_sn[cnt] = dn;                            // self-loop source = dst node
    }
    __syncthreads();
    // sweep1: 8 attention dots per entry (warp per entry)
    for (int ent = wid; ent <= cnt; ent += 8) {
        const float4* xr4 = (const float4*)(x + (size_t)s_sn[ent] * F_IN);
        float4 a4 = xr4[lane * 2];
        float4 b4 = xr4[lane * 2 + 1];
        float xv[8] = {a4.x, a4.y, a4.z, a4.w, b4.x, b4.y, b4.z, b4.w};
        float p[8] = {0.f, 0.f, 0.f, 0.f, 0.f, 0.f, 0.f, 0.f};
        #pragma unroll
        for (int q = 0; q < 8; q++) {
            const float4* wv4 = (const float4*)&g_wv[(lane * 8 + q) * 8];
            float4 w0 = wv4[0], w1 = wv4[1];
            p[0] += xv[q] * w0.x; p[1] += xv[q] * w0.y;
            p[2] += xv[q] * w0.z; p[3] += xv[q] * w0.w;
            p[4] += xv[q] * w1.x; p[5] += xv[q] * w1.y;
            p[6] += xv[q] * w1.z; p[7] += xv[q] * w1.w;
        }
        #pragma unroll
        for (int j = 0; j < 8; j++) {
            float s = p[j];
            #pragma unroll
            for (int off = 16; off > 0; off >>= 1) s += __shfl_down_sync(0xffffffffu, s, off);
            p[j] = s;
        }
        if (lane == 0) {
            *(float4*)&s_an[ent * 8]     = make_float4(p[0], p[1], p[2], p[3]);
            *(float4*)&s_an[ent * 8 + 4] = make_float4(p[4], p[5], p[6], p[7]);
        }
    }
    __syncthreads();
    // logits (+ea-logit recompute, ea L2-hot) -> leaky
    if (tid < cnt) {
        const float4* r = (const float4*)(ea + (size_t)s_eid[tid] * DE);
        float l0 = 0.f, l1 = 0.f, l2 = 0.f, l3 = 0.f;
        #pragma unroll
        for (int q = 0; q < 4; q++) {
            float4 v = r[q];
            const float* w = &s_wE[q * 4 * NHEAD];
            l0 += v.x * w[0] + v.y * w[4] + v.z * w[8]  + v.w * w[12];
            l1 += v.x * w[1] + v.y * w[5] + v.z * w[9]  + v.w * w[13];
            l2 += v.x * w[2] + v.y * w[6] + v.z * w[10] + v.w * w[14];
            l3 += v.x * w[3] + v.y * w[7] + v.z * w[11] + v.w * w[15];
        }
        float le[4] = {l0, l1, l2, l3};
        #pragma unroll
        for (int h = 0; h < NHEAD; h++) {
            float l = s_an[tid * 8 + h] + s_an[cnt * 8 + 4 + h] + le[h];
            s_w[tid * 4 + h] = (l > 0.f) ? l : SLOPE_ATT * l;
        }
    } else if (tid == cnt) {
        #pragma unroll
        for (int h = 0; h < NHEAD; h++) {
            float l = s_an[cnt * 8 + h] + s_an[cnt * 8 + 4 + h] + s_aloop[h];
            s_w[cnt * 4 + h] = (l > 0.f) ? l : SLOPE_ATT * l;
        }
    }
    __syncthreads();
    const int total = cnt + 1;
    if (tid < NHEAD) {
        float m = -3.0e38f;
        for (int e = 0; e < total; e++) m = fmaxf(m, s_w[e * 4 + tid]);
        float su = 0.f;
        for (int e = 0; e < total; e++) { float w = __expf(s_w[e * 4 + tid] - m); s_w[e * 4 + tid] = w; su += w; }
        s_inv[tid] = 1.f / (su + 1e-16f);
    }
    __syncthreads();
    // sweep2: x-space aggregation (x rows L1-hot from sweep1)
    float acc0 = 0.f, acc1 = 0.f, acc2 = 0.f, acc3 = 0.f;
    for (int e = 0; e < total; e++) {
        float xv = x[(size_t)s_sn[e] * F_IN + tid];
        acc0 += s_w[e * 4 + 0] * xv;
        acc1 += s_w[e * 4 + 1] * xv;
        acc2 += s_w[e * 4 + 2] * xv;
        acc3 += s_w[e * 4 + 3] * xv;
    }
    float* xo = &g_xagg[(size_t)dc * NHEAD * F_IN];
    xo[0 * F_IN + tid] = acc0 * s_inv[0];
    xo[1 * F_IN + tid] = acc1 * s_inv[1];
    xo[2 * F_IN + tid] = acc2 * s_inv[2];
    xo[3 * F_IN + tid] = acc3 * s_inv[3];
}

// ================= K3: hact = leaky(xagg @ W + bias) ========================
// 288 blocks: (dst group of 8, head/col-group of 128). warp = row, lane = 4 cols.
__global__ void __launch_bounds__(256)
k_gat(const float* __restrict__ W, const float* __restrict__ bias)
{
    __shared__ float xa[8 * F_IN];
    const int g = blockIdx.x >> 2, cg = blockIdx.x & 3;
    const int tid = threadIdx.x;
    const int wid = tid >> 5, lane = tid & 31;
    if (blockIdx.x == 0 && tid < DE) g_easum[tid] = 0.f;   // restore for replay
    for (int i = tid; i < 8 * F_IN; i += 256)
        xa[i] = g_xagg[(size_t)(g * 8 + (i >> 8)) * NHEAD * F_IN + cg * F_IN + (i & (F_IN - 1))];
    __syncthreads();
    const int n = cg * 128 + lane * 4;
    float4 acc = make_float4(0.f, 0.f, 0.f, 0.f);
    #pragma unroll 4
    for (int k = 0; k < F_IN; k++) {
        float xv = xa[wid * F_IN + k];                      // broadcast LDS
        float4 w4 = *(const float4*)(W + (size_t)k * HC + n);
        acc.x += xv * w4.x; acc.y += xv * w4.y;
        acc.z += xv * w4.z; acc.w += xv * w4.w;
    }
    float4 b4 = *(const float4*)(bias + n);
    acc.x += b4.x; acc.y += b4.y; acc.z += b4.z; acc.w += b4.w;
    acc.x = (acc.x > 0.f) ? acc.x : SLOPE * acc.x;
    acc.y = (acc.y > 0.f) ? acc.y : SLOPE * acc.y;
    acc.z = (acc.z > 0.f) ? acc.z : SLOPE * acc.z;
    acc.w = (acc.w > 0.f) ? acc.w : SLOPE * acc.w;
    *(float4*)&g_hact[(size_t)(g * 8 + wid) * HC + n] = acc;
}

// ================= K4: out = leaky(hact @ fcW + fcb) ========================
// 144 blocks: (dst group of 8, out col half of 128). warp = row, lane = 4 cols.
__global__ void __launch_bounds__(256)
k_fc(const float* __restrict__ fcW, const float* __restrict__ fcb,
     float* __restrict__ out)
{
    __shared__ float hs[8 * HC];
    const int g = blockIdx.x >> 1, og = blockIdx.x & 1;
    const int tid = threadIdx.x;
    const int wid = tid >> 5, lane = tid & 31;
    for (int i = tid; i < 8 * HC; i += 256)
        hs[i] = g_hact[(size_t)(g * 8 + (i >> 9)) * HC + (i & (HC - 1))];
    __syncthreads();
    const int n = og * 128 + lane * 4;
    float4 acc = make_float4(0.f, 0.f, 0.f, 0.f);
    #pragma unroll 4
    for (int k = 0; k < HC; k++) {
        float hv = hs[wid * HC + k];                        // broadcast LDS
        float4 f4 = *(const float4*)(fcW + (size_t)k * HID + n);
        acc.x += hv * f4.x; acc.y += hv * f4.y;
        acc.z += hv * f4.z; acc.w += hv * f4.w;
    }
    float4 b4 = *(const float4*)(fcb + n);
    acc.x += b4.x; acc.y += b4.y; acc.z += b4.z; acc.w += b4.w;
    acc.x = (acc.x > 0.f) ? acc.x : SLOPE * acc.x;
    acc.y = (acc.y > 0.f) ? acc.y : SLOPE * acc.y;
    acc.z = (acc.z > 0.f) ? acc.z : SLOPE * acc.z;
    acc.w = (acc.w > 0.f) ? acc.w : SLOPE * acc.w;
    *(float4*)&out[(size_t)(g * 8 + wid) * HID + n] = acc;
}

// ---------------- launch ----------------
extern "C" void kernel_launch(void* const* d_in, const int* in_sizes, int n_in,
                              void* d_out, int out_size) {
    const float* x        = (const float*)d_in[0];
    const int*   ei       = (const int*)d_in[1];
    const float* ea       = (const float*)d_in[2];
    const float* W        = (const float*)d_in[5];
    const float* att_src  = (const float*)d_in[6];
    const float* att_dst  = (const float*)d_in[7];
    const float* W_edge   = (const float*)d_in[8];
    const float* att_edge = (const float*)d_in[9];
    const float* bias     = (const float*)d_in[10];
    const float* fcW      = (const float*)d_in[11];
    const float* fcb      = (const float*)d_in[12];
    float* out = (float*)d_out;
    const int E = in_sizes[1] / 2;
    const int nslab = (E + EPB - 1) / EPB;

    k_prep<<<nslab + 264, 256>>>(ei, ea, W, att_src, att_dst, W_edge, att_edge, E, nslab);
    k_dst<<<NOUT, 256>>>(x, ea, 1.0f / (float)E);
    k_gat<<<(NOUT / 8) * 4, 256>>>(W, bias);
    k_fc<<<(NOUT / 8) * 2, 256>>>(fcW, fcb, out);
}

// round 13
// speedup vs baseline: 1.1876x; 1.1802x over previous
#include <cuda_runtime.h>
#include <cstdint>
#include <math.h>

// ---------------- problem constants ----------------
#define N_NODES 27648
#define F_IN    256
#define HC      512
#define NHEAD   4
#define CDIM    128
#define DE      16
#define HID     256
#define NA      48
#define NOUT    576
#define CAP     64
#define SLOPE_ATT 0.2f
#define SLOPE     0.01f
#define EPB     512

// ---------------- device scratch ----------------
__device__ float g_wv[F_IN * 8];                // wv[f][j]: j<4 src head, j>=4 dst head
__device__ float g_wattE[DE * NHEAD];
__device__ float g_easum[DE];                   // zero-init; reset by k_gat each replay
__device__ int   g_dstcnt[NOUT];                // zero-init; reset by k_dst each replay
__device__ int   g_ebsrc[NOUT * CAP];           // src node ids
__device__ int   g_ebeid[NOUT * CAP];           // edge ids
__device__ float g_xagg[NOUT * NHEAD * F_IN];   // per-dst per-head aggregated x
__device__ float g_hact[NOUT * HC];

__device__ __forceinline__ int diag_node(int i) { return (i / NA) * (NA * NA) + (i % NA) * (NA + 1); }

// ================= K1: prep — wv + wattE + easum + scan/bucket ==============
__global__ void __launch_bounds__(256)
k_prep(const int* __restrict__ ei, const float* __restrict__ ea,
       const float* __restrict__ W, const float* __restrict__ att_src,
       const float* __restrict__ att_dst, const float* __restrict__ W_edge,
       const float* __restrict__ att_edge, int E, int nslab)
{
    const int tid = threadIdx.x;
    const int wid = tid >> 5, lane = tid & 31;
    const int bid = blockIdx.x;

    if (bid < nslab) {
        __shared__ float s_ea[DE];
        if (tid < DE) s_ea[tid] = 0.f;
        __syncthreads();
        const int ebase = bid * EPB;
        {
            const float4* ea4 = (const float4*)ea;
            const int g0 = ebase * 4;
            const int lim4 = E * 4;
            float4 acc = make_float4(0.f, 0.f, 0.f, 0.f);
            #pragma unroll
            for (int i = 0; i < EPB * 4 / 256; i++) {
                int g4 = g0 + tid + i * 256;
                if (g4 < lim4) {
                    float4 v = ea4[g4];
                    acc.x += v.x; acc.y += v.y; acc.z += v.z; acc.w += v.w;
                }
            }
            int d0 = (tid & 3) * 4;
            atomicAdd(&s_ea[d0 + 0], acc.x);
            atomicAdd(&s_ea[d0 + 1], acc.y);
            atomicAdd(&s_ea[d0 + 2], acc.z);
            atomicAdd(&s_ea[d0 + 3], acc.w);
        }
        if (tid < EPB / 4) {
            const int* dst = ei + E;
            const int e0 = ebase + tid * 4;
            if (e0 + 3 < E) {
                int4 d4 = *(const int4*)(dst + e0);
                #pragma unroll
                for (int j = 0; j < 4; j++) {
                    int d = (j == 0) ? d4.x : (j == 1) ? d4.y : (j == 2) ? d4.z : d4.w;
                    int rem = d % (NA * NA);
                    if (rem % (NA + 1) == 0) {
                        int e = e0 + j;
                        int dc = (d / (NA * NA)) * NA + rem / (NA + 1);
                        int p = atomicAdd(&g_dstcnt[dc], 1);
                        if (p < CAP) {
                            g_ebsrc[dc * CAP + p] = ei[e];
                            g_ebeid[dc * CAP + p] = e;
                        }
                    }
                }
            } else {
                for (int j = 0; j < 4; j++) {
                    int e = e0 + j;
                    if (e >= E) break;
                    int d = dst[e];
                    int rem = d % (NA * NA);
                    if (rem % (NA + 1) == 0) {
                        int dc = (d / (NA * NA)) * NA + rem / (NA + 1);
                        int p = atomicAdd(&g_dstcnt[dc], 1);
                        if (p < CAP) {
                            g_ebsrc[dc * CAP + p] = ei[e];
                            g_ebeid[dc * CAP + p] = e;
                        }
                    }
                }
            }
        }
        __syncthreads();
        if (tid < DE) atomicAdd(&g_easum[tid], s_ea[tid]);
    } else if (bid < nslab + 256) {
        int pair = (bid - nslab) * 8 + wid;       // < 2048
        int f = pair >> 3, j = pair & 7, h = j & 3;
        const float* att = ((j < 4) ? att_src : att_dst) + h * CDIM;
        float4 w4 = *(const float4*)(W + (size_t)f * HC + h * CDIM + lane * 4);
        float4 a4 = *(const float4*)(att + lane * 4);
        float s = w4.x * a4.x + w4.y * a4.y + w4.z * a4.z + w4.w * a4.w;
        #pragma unroll
        for (int off = 16; off > 0; off >>= 1) s += __shfl_down_sync(0xffffffffu, s, off);
        if (lane == 0) g_wv[f * 8 + j] = s;
    } else {
        int pair = (bid - nslab - 256) * 8 + wid; // < 64
        int d = pair >> 2, h = pair & 3;
        float4 w4 = *(const float4*)(W_edge + (size_t)d * HC + h * CDIM + lane * 4);
        float4 a4 = *(const float4*)(att_edge + h * CDIM + lane * 4);
        float s = w4.x * a4.x + w4.y * a4.y + w4.z * a4.z + w4.w * a4.w;
        #pragma unroll
        for (int off = 16; off > 0; off >>= 1) s += __shfl_down_sync(0xffffffffu, s, off);
        if (lane == 0) g_wattE[pair] = s;
    }
}

// ================= K2: per-dst scores + softmax + x-aggregation =============
__global__ void __launch_bounds__(256)
k_dst(const float* __restrict__ x, const float* __restrict__ ea, float invE)
{
    const int dc = blockIdx.x;
    const int tid = threadIdx.x;
    const int wid = tid >> 5, lane = tid & 31;
    __shared__ float s_an[(CAP + 1) * 8];
    __shared__ float s_w[(CAP + 1) * NHEAD];
    __shared__ float s_wE[DE * NHEAD];
    __shared__ float s_aloop[NHEAD];
    __shared__ float s_inv[NHEAD];
    __shared__ int   s_sn[CAP + 1];
    __shared__ int   s_eid[CAP];
    __shared__ int   s_cnt;

    if (tid < DE * NHEAD) s_wE[tid] = g_wattE[tid];
    if (tid == 0) {
        int c = g_dstcnt[dc];
        s_cnt = c < CAP ? c : CAP;
        g_dstcnt[dc] = 0;                          // restore for next replay
    }
    __syncthreads();
    if (tid < NHEAD) {
        float a = 0.f;
        #pragma unroll
        for (int d = 0; d < DE; d++) a += g_easum[d] * invE * s_wE[d * NHEAD + tid];
        s_aloop[tid] = a;
    }
    const int cnt = s_cnt;
    const int dn = diag_node(dc);
    if (tid < cnt) {
        s_sn[tid] = g_ebsrc[dc * CAP + tid];
        s_eid[tid] = g_ebeid[dc * CAP + tid];
    } else if (tid == cnt) {
        s_sn[cnt] = dn;                            // self-loop source = dst node
    }
    __syncthreads();
    // sweep1: 8 attention dots per entry (warp per entry)
    for (int ent = wid; ent <= cnt; ent += 8) {
        const float4* xr4 = (const float4*)(x + (size_t)s_sn[ent] * F_IN);
        float4 a4 = xr4[lane * 2];
        float4 b4 = xr4[lane * 2 + 1];
        float xv[8] = {a4.x, a4.y, a4.z, a4.w, b4.x, b4.y, b4.z, b4.w};
        float p[8] = {0.f, 0.f, 0.f, 0.f, 0.f, 0.f, 0.f, 0.f};
        #pragma unroll
        for (int q = 0; q < 8; q++) {
            const float4* wv4 = (const float4*)&g_wv[(lane * 8 + q) * 8];
            float4 w0 = wv4[0], w1 = wv4[1];
            p[0] += xv[q] * w0.x; p[1] += xv[q] * w0.y;
            p[2] += xv[q] * w0.z; p[3] += xv[q] * w0.w;
            p[4] += xv[q] * w1.x; p[5] += xv[q] * w1.y;
            p[6] += xv[q] * w1.z; p[7] += xv[q] * w1.w;
        }
        #pragma unroll
        for (int j = 0; j < 8; j++) {
            float s = p[j];
            #pragma unroll
            for (int off = 16; off > 0; off >>= 1) s += __shfl_down_sync(0xffffffffu, s, off);
            p[j] = s;
        }
        if (lane == 0) {
            *(float4*)&s_an[ent * 8]     = make_float4(p[0], p[1], p[2], p[3]);
            *(float4*)&s_an[ent * 8 + 4] = make_float4(p[4], p[5], p[6], p[7]);
        }
    }
    __syncthreads();
    // logits (+ea-logit recompute, ea L2-hot) -> leaky
    if (tid < cnt) {
        const float4* r = (const float4*)(ea + (size_t)s_eid[tid] * DE);
        float l0 = 0.f, l1 = 0.f, l2 = 0.f, l3 = 0.f;
        #pragma unroll
        for (int q = 0; q < 4; q++) {
            float4 v = r[q];
            const float* w = &s_wE[q * 4 * NHEAD];
            l0 += v.x * w[0] + v.y * w[4] + v.z * w[8]  + v.w * w[12];
            l1 += v.x * w[1] + v.y * w[5] + v.z * w[9]  + v.w * w[13];
            l2 += v.x * w[2] + v.y * w[6] + v.z * w[10] + v.w * w[14];
            l3 += v.x * w[3] + v.y * w[7] + v.z * w[11] + v.w * w[15];
        }
        float le[4] = {l0, l1, l2, l3};
        #pragma unroll
        for (int h = 0; h < NHEAD; h++) {
            float l = s_an[tid * 8 + h] + s_an[cnt * 8 + 4 + h] + le[h];
            s_w[tid * 4 + h] = (l > 0.f) ? l : SLOPE_ATT * l;
        }
    } else if (tid == cnt) {
        #pragma unroll
        for (int h = 0; h < NHEAD; h++) {
            float l = s_an[cnt * 8 + h] + s_an[cnt * 8 + 4 + h] + s_aloop[h];
            s_w[cnt * 4 + h] = (l > 0.f) ? l : SLOPE_ATT * l;
        }
    }
    __syncthreads();
    const int total = cnt + 1;
    if (tid < NHEAD) {
        float m = -3.0e38f;
        for (int e = 0; e < total; e++) m = fmaxf(m, s_w[e * 4 + tid]);
        float su = 0.f;
        for (int e = 0; e < total; e++) { float w = __expf(s_w[e * 4 + tid] - m); s_w[e * 4 + tid] = w; su += w; }
        s_inv[tid] = 1.f / (su + 1e-16f);
    }
    __syncthreads();
    // sweep2: x-space aggregation (x rows L1-hot from sweep1)
    float acc0 = 0.f, acc1 = 0.f, acc2 = 0.f, acc3 = 0.f;
    for (int e = 0; e < total; e++) {
        float xv = x[(size_t)s_sn[e] * F_IN + tid];
        acc0 += s_w[e * 4 + 0] * xv;
        acc1 += s_w[e * 4 + 1] * xv;
        acc2 += s_w[e * 4 + 2] * xv;
        acc3 += s_w[e * 4 + 3] * xv;
    }
    float* xo = &g_xagg[(size_t)dc * NHEAD * F_IN];
    xo[0 * F_IN + tid] = acc0 * s_inv[0];
    xo[1 * F_IN + tid] = acc1 * s_inv[1];
    xo[2 * F_IN + tid] = acc2 * s_inv[2];
    xo[3 * F_IN + tid] = acc3 * s_inv[3];
}

// ================= K3: hact = leaky(xagg @ W + bias) ========================
// 576 blocks: (g: 144 groups of 4 rows) x (cg: 4 col groups of 128).
// 8 warps = (row 0..3) x (k-half 0..1), each warp K=128, unroll 8.
__global__ void __launch_bounds__(256)
k_gat(const float* __restrict__ W, const float* __restrict__ bias)
{
    __shared__ float xa[4 * F_IN];        // 4KB
    __shared__ float s_part[8 * 128];     // 4KB
    const int g = blockIdx.x >> 2, cg = blockIdx.x & 3;
    const int tid = threadIdx.x;
    const int wid = tid >> 5, lane = tid & 31;
    if (blockIdx.x == 0 && tid < DE) g_easum[tid] = 0.f;   // restore for replay
    for (int i = tid; i < 4 * F_IN; i += 256)
        xa[i] = g_xagg[(size_t)(g * 4 + (i >> 8)) * NHEAD * F_IN + cg * F_IN + (i & (F_IN - 1))];
    __syncthreads();
    const int r = wid & 3, kh = wid >> 2;
    const int n = cg * 128 + lane * 4;
    const int k0 = kh * 128;
    float4 acc = make_float4(0.f, 0.f, 0.f, 0.f);
    #pragma unroll 8
    for (int k = k0; k < k0 + 128; k++) {
        float xv = xa[r * F_IN + k];
        float4 w4 = *(const float4*)(W + (size_t)k * HC + n);
        acc.x += xv * w4.x; acc.y += xv * w4.y;
        acc.z += xv * w4.z; acc.w += xv * w4.w;
    }
    *(float4*)&s_part[wid * 128 + lane * 4] = acc;
    __syncthreads();
    if (tid < 128) {
        const int rr = tid >> 5, q = tid & 31;
        float4 p0 = *(const float4*)&s_part[rr * 128 + q * 4];
        float4 p1 = *(const float4*)&s_part[(4 + rr) * 128 + q * 4];
        float4 b4 = *(const float4*)(bias + cg * 128 + q * 4);
        float4 v;
        v.x = p0.x + p1.x + b4.x; v.y = p0.y + p1.y + b4.y;
        v.z = p0.z + p1.z + b4.z; v.w = p0.w + p1.w + b4.w;
        v.x = (v.x > 0.f) ? v.x : SLOPE * v.x;
        v.y = (v.y > 0.f) ? v.y : SLOPE * v.y;
        v.z = (v.z > 0.f) ? v.z : SLOPE * v.z;
        v.w = (v.w > 0.f) ? v.w : SLOPE * v.w;
        *(float4*)&g_hact[(size_t)(g * 4 + rr) * HC + cg * 128 + q * 4] = v;
    }
}

// ================= K4: out = leaky(hact @ fcW + fcb) ========================
// 288 blocks: (g: 144 groups of 4 rows) x (og: 2 col halves of 128).
// 8 warps = (row 0..3) x (k-half 0..1), each warp K=256, unroll 8.
__global__ void __launch_bounds__(256)
k_fc(const float* __restrict__ fcW, const float* __restrict__ fcb,
     float* __restrict__ out)
{
    __shared__ float hs[4 * HC];          // 8KB
    __shared__ float s_part[8 * 128];     // 4KB
    const int g = blockIdx.x >> 1, og = blockIdx.x & 1;
    const int tid = threadIdx.x;
    const int wid = tid >> 5, lane = tid & 31;
    for (int i = tid; i < 4 * HC; i += 256)
        hs[i] = g_hact[(size_t)(g * 4 + (i >> 9)) * HC + (i & (HC - 1))];
    __syncthreads();
    const int r = wid & 3, kh = wid >> 2;
    const int n = og * 128 + lane * 4;
    const int k0 = kh * 256;
    float4 acc = make_float4(0.f, 0.f, 0.f, 0.f);
    #pragma unroll 8
    for (int k = k0; k < k0 + 256; k++) {
        float hv = hs[r * HC + k];
        float4 f4 = *(const float4*)(fcW + (size_t)k * HID + n);
        acc.x += hv * f4.x; acc.y += hv * f4.y;
        acc.z += hv * f4.z; acc.w += hv * f4.w;
    }
    *(float4*)&s_part[wid * 128 + lane * 4] = acc;
    __syncthreads();
    if (tid < 128) {
        const int rr = tid >> 5, q = tid & 31;
        float4 p0 = *(const float4*)&s_part[rr * 128 + q * 4];
        float4 p1 = *(const float4*)&s_part[(4 + rr) * 128 + q * 4];
        float4 b4 = *(const float4*)(fcb + og * 128 + q * 4);
        float4 v;
        v.x = p0.x + p1.x + b4.x; v.y = p0.y + p1.y + b4.y;
        v.z = p0.z + p1.z + b4.z; v.w = p0.w + p1.w + b4.w;
        v.x = (v.x > 0.f) ? v.x : SLOPE * v.x;
        v.y = (v.y > 0.f) ? v.y : SLOPE * v.y;
        v.z = (v.z > 0.f) ? v.z : SLOPE * v.z;
        v.w = (v.w > 0.f) ? v.w : SLOPE * v.w;
        *(float4*)&out[(size_t)(g * 4 + rr) * HID + og * 128 + q * 4] = v;
    }
}

// ---------------- launch ----------------
extern "C" void kernel_launch(void* const* d_in, const int* in_sizes, int n_in,
                              void* d_out, int out_size) {
    const float* x        = (const float*)d_in[0];
    const int*   ei       = (const int*)d_in[1];
    const float* ea       = (const float*)d_in[2];
    const float* W        = (const float*)d_in[5];
    const float* att_src  = (const float*)d_in[6];
    const float* att_dst  = (const float*)d_in[7];
    const float* W_edge   = (const float*)d_in[8];
    const float* att_edge = (const float*)d_in[9];
    const float* bias     = (const float*)d_in[10];
    const float* fcW      = (const float*)d_in[11];
    const float* fcb      = (const float*)d_in[12];
    float* out = (float*)d_out;
    const int E = in_sizes[1] / 2;
    const int nslab = (E + EPB - 1) / EPB;

    k_prep<<<nslab + 264, 256>>>(ei, ea, W, att_src, att_dst, W_edge, att_edge, E, nslab);
    k_dst<<<NOUT, 256>>>(x, ea, 1.0f / (float)E);
    k_gat<<<(NOUT / 4) * 4, 256>>>(W, bias);
    k_fc<<<(NOUT / 4) * 2, 256>>>(fcW, fcb, out);
}

// round 14
// speedup vs baseline: 1.4472x; 1.2186x over previous
#include <cuda_runtime.h>
#include <cstdint>
#include <math.h>

// ---------------- problem constants ----------------
#define N_NODES 27648
#define F_IN    256
#define HC      512
#define NHEAD   4
#define DE      16
#define HID     256
#define NA      48
#define NOUT    576
#define CAP     64
#define SLOPE_ATT 0.2f
#define SLOPE     0.01f
#define EPB     512

// ---------------- device scratch ----------------
__device__ float g_wv[F_IN * 8];                // wv[f][j]: j<4 src head, j>=4 dst head
__device__ float g_wattE[DE * NHEAD];
__device__ float g_easum[DE];                   // zero-init; reset by k_gemm<0> each replay
__device__ int   g_dstcnt[NOUT];                // zero-init; reset by k_dst each replay
__device__ int   g_ebsrc[NOUT * CAP];           // src node ids
__device__ int   g_ebeid[NOUT * CAP];           // edge ids
__device__ float g_xagg[NOUT * NHEAD * F_IN];   // per-dst per-head aggregated x
__device__ float g_hact[NOUT * HC];

__device__ __forceinline__ int diag_node(int i) { return (i / NA) * (NA * NA) + (i % NA) * (NA + 1); }

// ================= K1: prep — wv + wattE + easum + scan/bucket ==============
__global__ void __launch_bounds__(256)
k_prep(const int* __restrict__ ei, const float* __restrict__ ea,
       const float* __restrict__ W, const float* __restrict__ att_src,
       const float* __restrict__ att_dst, const float* __restrict__ W_edge,
       const float* __restrict__ att_edge, int E, int nslab)
{
    const int tid = threadIdx.x;
    const int wid = tid >> 5, lane = tid & 31;
    const int bid = blockIdx.x;

    if (bid < nslab) {
        __shared__ float s_ea[DE];
        if (tid < DE) s_ea[tid] = 0.f;
        __syncthreads();
        const int ebase = bid * EPB;
        {
            const float4* ea4 = (const float4*)ea;
            const int g0 = ebase * 4;
            const int lim4 = E * 4;
            float4 acc = make_float4(0.f, 0.f, 0.f, 0.f);
            #pragma unroll
            for (int i = 0; i < EPB * 4 / 256; i++) {
                int g4 = g0 + tid + i * 256;
                if (g4 < lim4) {
                    float4 v = ea4[g4];
                    acc.x += v.x; acc.y += v.y; acc.z += v.z; acc.w += v.w;
                }
            }
            int d0 = (tid & 3) * 4;
            atomicAdd(&s_ea[d0 + 0], acc.x);
            atomicAdd(&s_ea[d0 + 1], acc.y);
            atomicAdd(&s_ea[d0 + 2], acc.z);
            atomicAdd(&s_ea[d0 + 3], acc.w);
        }
        if (tid < EPB / 4) {
            const int* dst = ei + E;
            const int e0 = ebase + tid * 4;
            if (e0 + 3 < E) {
                int4 d4 = *(const int4*)(dst + e0);
                #pragma unroll
                for (int j = 0; j < 4; j++) {
                    int d = (j == 0) ? d4.x : (j == 1) ? d4.y : (j == 2) ? d4.z : d4.w;
                    int rem = d % (NA * NA);
                    if (rem % (NA + 1) == 0) {
                        int e = e0 + j;
                        int dc = (d / (NA * NA)) * NA + rem / (NA + 1);
                        int p = atomicAdd(&g_dstcnt[dc], 1);
                        if (p < CAP) {
                            g_ebsrc[dc * CAP + p] = ei[e];
                            g_ebeid[dc * CAP + p] = e;
                        }
                    }
                }
            } else {
                for (int j = 0; j < 4; j++) {
                    int e = e0 + j;
                    if (e >= E) break;
                    int d = dst[e];
                    int rem = d % (NA * NA);
                    if (rem % (NA + 1) == 0) {
                        int dc = (d / (NA * NA)) * NA + rem / (NA + 1);
                        int p = atomicAdd(&g_dstcnt[dc], 1);
                        if (p < CAP) {
                            g_ebsrc[dc * CAP + p] = ei[e];
                            g_ebeid[dc * CAP + p] = e;
                        }
                    }
                }
            }
        }
        __syncthreads();
        if (tid < DE) atomicAdd(&g_easum[tid], s_ea[tid]);
    } else if (bid < nslab + 256) {
        int pair = (bid - nslab) * 8 + wid;       // < 2048
        int f = pair >> 3, j = pair & 7, h = j & 3;
        const float* att = ((j < 4) ? att_src : att_dst) + h * 128;
        float4 w4 = *(const float4*)(W + (size_t)f * HC + h * 128 + lane * 4);
        float4 a4 = *(const float4*)(att + lane * 4);
        float s = w4.x * a4.x + w4.y * a4.y + w4.z * a4.z + w4.w * a4.w;
        #pragma unroll
        for (int off = 16; off > 0; off >>= 1) s += __shfl_down_sync(0xffffffffu, s, off);
        if (lane == 0) g_wv[f * 8 + j] = s;
    } else {
        int pair = (bid - nslab - 256) * 8 + wid; // < 64
        int d = pair >> 2, h = pair & 3;
        float4 w4 = *(const float4*)(W_edge + (size_t)d * HC + h * 128 + lane * 4);
        float4 a4 = *(const float4*)(att_edge + h * 128 + lane * 4);
        float s = w4.x * a4.x + w4.y * a4.y + w4.z * a4.z + w4.w * a4.w;
        #pragma unroll
        for (int off = 16; off > 0; off >>= 1) s += __shfl_down_sync(0xffffffffu, s, off);
        if (lane == 0) g_wattE[pair] = s;
    }
}

// ================= K2: per-dst scores + softmax + x-aggregation =============
__global__ void __launch_bounds__(256)
k_dst(const float* __restrict__ x, const float* __restrict__ ea, float invE)
{
    const int dc = blockIdx.x;
    const int tid = threadIdx.x;
    const int wid = tid >> 5, lane = tid & 31;
    __shared__ float s_an[(CAP + 1) * 8];
    __shared__ float s_w[(CAP + 1) * NHEAD];
    __shared__ float s_wE[DE * NHEAD];
    __shared__ float s_aloop[NHEAD];
    __shared__ float s_inv[NHEAD];
    __shared__ int   s_sn[CAP + 1];
    __shared__ int   s_eid[CAP];
    __shared__ int   s_cnt;

    if (tid < DE * NHEAD) s_wE[tid] = g_wattE[tid];
    if (tid == 0) {
        int c = g_dstcnt[dc];
        s_cnt = c < CAP ? c : CAP;
        g_dstcnt[dc] = 0;                          // restore for next replay
    }
    __syncthreads();
    if (tid < NHEAD) {
        float a = 0.f;
        #pragma unroll
        for (int d = 0; d < DE; d++) a += g_easum[d] * invE * s_wE[d * NHEAD + tid];
        s_aloop[tid] = a;
    }
    const int cnt = s_cnt;
    const int dn = diag_node(dc);
    if (tid < cnt) {
        s_sn[tid] = g_ebsrc[dc * CAP + tid];
        s_eid[tid] = g_ebeid[dc * CAP + tid];
    } else if (tid == cnt) {
        s_sn[cnt] = dn;                            // self-loop source = dst node
    }
    __syncthreads();
    // sweep1: 8 attention dots per entry (warp per entry)
    for (int ent = wid; ent <= cnt; ent += 8) {
        const float4* xr4 = (const float4*)(x + (size_t)s_sn[ent] * F_IN);
        float4 a4 = xr4[lane * 2];
        float4 b4 = xr4[lane * 2 + 1];
        float xv[8] = {a4.x, a4.y, a4.z, a4.w, b4.x, b4.y, b4.z, b4.w};
        float p[8] = {0.f, 0.f, 0.f, 0.f, 0.f, 0.f, 0.f, 0.f};
        #pragma unroll
        for (int q = 0; q < 8; q++) {
            const float4* wv4 = (const float4*)&g_wv[(lane * 8 + q) * 8];
            float4 w0 = wv4[0], w1 = wv4[1];
            p[0] += xv[q] * w0.x; p[1] += xv[q] * w0.y;
            p[2] += xv[q] * w0.z; p[3] += xv[q] * w0.w;
            p[4] += xv[q] * w1.x; p[5] += xv[q] * w1.y;
            p[6] += xv[q] * w1.z; p[7] += xv[q] * w1.w;
        }
        #pragma unroll
        for (int j = 0; j < 8; j++) {
            float s = p[j];
            #pragma unroll
            for (int off = 16; off > 0; off >>= 1) s += __shfl_down_sync(0xffffffffu, s, off);
            p[j] = s;
        }
        if (lane == 0) {
            *(float4*)&s_an[ent * 8]     = make_float4(p[0], p[1], p[2], p[3]);
            *(float4*)&s_an[ent * 8 + 4] = make_float4(p[4], p[5], p[6], p[7]);
        }
    }
    __syncthreads();
    // logits (+ea-logit recompute, ea L2-hot) -> leaky
    if (tid < cnt) {
        const float4* r = (const float4*)(ea + (size_t)s_eid[tid] * DE);
        float l0 = 0.f, l1 = 0.f, l2 = 0.f, l3 = 0.f;
        #pragma unroll
        for (int q = 0; q < 4; q++) {
            float4 v = r[q];
            const float* w = &s_wE[q * 4 * NHEAD];
            l0 += v.x * w[0] + v.y * w[4] + v.z * w[8]  + v.w * w[12];
            l1 += v.x * w[1] + v.y * w[5] + v.z * w[9]  + v.w * w[13];
            l2 += v.x * w[2] + v.y * w[6] + v.z * w[10] + v.w * w[14];
            l3 += v.x * w[3] + v.y * w[7] + v.z * w[11] + v.w * w[15];
        }
        float le[4] = {l0, l1, l2, l3};
        #pragma unroll
        for (int h = 0; h < NHEAD; h++) {
            float l = s_an[tid * 8 + h] + s_an[cnt * 8 + 4 + h] + le[h];
            s_w[tid * 4 + h] = (l > 0.f) ? l : SLOPE_ATT * l;
        }
    } else if (tid == cnt) {
        #pragma unroll
        for (int h = 0; h < NHEAD; h++) {
            float l = s_an[cnt * 8 + h] + s_an[cnt * 8 + 4 + h] + s_aloop[h];
            s_w[cnt * 4 + h] = (l > 0.f) ? l : SLOPE_ATT * l;
        }
    }
    __syncthreads();
    const int total = cnt + 1;
    if (tid < NHEAD) {
        float m = -3.0e38f;
        for (int e = 0; e < total; e++) m = fmaxf(m, s_w[e * 4 + tid]);
        float su = 0.f;
        for (int e = 0; e < total; e++) { float w = __expf(s_w[e * 4 + tid] - m); s_w[e * 4 + tid] = w; su += w; }
        s_inv[tid] = 1.f / (su + 1e-16f);
    }
    __syncthreads();
    // sweep2: x-space aggregation (x rows L1-hot from sweep1)
    float acc0 = 0.f, acc1 = 0.f, acc2 = 0.f, acc3 = 0.f;
    for (int e = 0; e < total; e++) {
        float xv = x[(size_t)s_sn[e] * F_IN + tid];
        acc0 += s_w[e * 4 + 0] * xv;
        acc1 += s_w[e * 4 + 1] * xv;
        acc2 += s_w[e * 4 + 2] * xv;
        acc3 += s_w[e * 4 + 3] * xv;
    }
    float* xo = &g_xagg[(size_t)dc * NHEAD * F_IN];
    xo[0 * F_IN + tid] = acc0 * s_inv[0];
    xo[1 * F_IN + tid] = acc1 * s_inv[1];
    xo[2 * F_IN + tid] = acc2 * s_inv[2];
    xo[3 * F_IN + tid] = acc3 * s_inv[3];
}

// ================= K3/K4: tiled GEMM + bias + leaky =========================
// MODE 0 (gat): C[576,512] = xagg(per-head) @ W,  K=256, 8 col tiles of 64
// MODE 1 (fc) : C[576,256] = hact @ fcW,          K=512, 4 col tiles of 64
// Tile: M=16, N=64, K-chunk=32; 256 threads; thread = (row pair, col pair).
// Dynamic smem: As 16*K(max 512) floats @0, Bs double buffer 2*2048 @32KB.
template<int MODE>
__global__ void __launch_bounds__(256)
k_gemm(const float* __restrict__ B, const float* __restrict__ bias,
       float* __restrict__ Cext)
{
    constexpr int K    = (MODE == 0) ? 256 : 512;
    constexpr int LDA  = (MODE == 0) ? 1024 : 512;
    constexpr int LDB  = (MODE == 0) ? 512 : 256;
    constexpr int LDC  = (MODE == 0) ? 512 : 256;
    constexpr int NCT  = (MODE == 0) ? 8 : 4;
    constexpr int NCH  = K / 32;
    constexpr int KSH  = (MODE == 0) ? 6 : 7;     // log2(K/4)

    extern __shared__ __align__(16) float sm[];
    float* As = sm;                 // 16 * K floats
    float* Bs = sm + 16 * 512;      // 2 * 2048 floats

    const int tid = threadIdx.x;
    const int bid = blockIdx.x;
    const int m0 = (bid / NCT) * 16;
    const int ct = bid % NCT;
    const int nbase = ct * 64;

    if (MODE == 0 && bid == 0 && tid < DE) g_easum[tid] = 0.f;  // replay restore

    const float* A = (MODE == 0) ? g_xagg : g_hact;
    float* C = (MODE == 0) ? g_hact : Cext;
    const int aoff = (MODE == 0) ? ((ct >> 1) * 256) : 0;

    // stage A: 16 rows x K
    #pragma unroll
    for (int i = tid; i < 4 * K; i += 256) {
        int r = i >> KSH;
        int k4 = i & ((K >> 2) - 1);
        ((float4*)(As + r * K))[k4] =
            ((const float4*)(A + (size_t)(m0 + r) * LDA + aoff))[k4];
    }
    // stage B chunk 0
    {
        int row = tid >> 4, c4 = tid & 15;
        ((float4*)Bs)[tid] = ((const float4*)(B + (size_t)row * LDB + nbase))[c4];
        ((float4*)Bs)[tid + 256] = ((const float4*)(B + (size_t)(row + 16) * LDB + nbase))[c4];
    }
    __syncthreads();

    const int rq = tid >> 5;            // 0..7 -> rows rq*2, rq*2+1
    const int cp = (tid & 31) * 2;      // col pair
    float acc00 = 0.f, acc01 = 0.f, acc10 = 0.f, acc11 = 0.f;

    #pragma unroll
    for (int c = 0; c < NCH; c++) {
        float4 p0, p1;
        if (c + 1 < NCH) {
            int row = tid >> 4, c4 = tid & 15;
            p0 = ((const float4*)(B + (size_t)((c + 1) * 32 + row) * LDB + nbase))[c4];
            p1 = ((const float4*)(B + (size_t)((c + 1) * 32 + row + 16) * LDB + nbase))[c4];
        }
        const float* Bb = Bs + (c & 1) * 2048;
        const float* Ar0 = As + (rq * 2) * K + c * 32;
        const float* Ar1 = Ar0 + K;
        #pragma unroll
        for (int kk = 0; kk < 32; kk++) {
            float2 bv = *(const float2*)&Bb[kk * 64 + cp];
            float a0 = Ar0[kk], a1 = Ar1[kk];
            acc00 += a0 * bv.x; acc01 += a0 * bv.y;
            acc10 += a1 * bv.x; acc11 += a1 * bv.y;
        }
        __syncthreads();
        if (c + 1 < NCH) {
            float* Bn = Bs + ((c + 1) & 1) * 2048;
            ((float4*)Bn)[tid] = p0;
            ((float4*)Bn)[tid + 256] = p1;
        }
        __syncthreads();
    }

    // epilogue
    const int col = nbase + cp;
    float2 b2 = *(const float2*)&bias[col];
    float v00 = acc00 + b2.x, v01 = acc01 + b2.y;
    float v10 = acc10 + b2.x, v11 = acc11 + b2.y;
    v00 = (v00 > 0.f) ? v00 : SLOPE * v00;
    v01 = (v01 > 0.f) ? v01 : SLOPE * v01;
    v10 = (v10 > 0.f) ? v10 : SLOPE * v10;
    v11 = (v11 > 0.f) ? v11 : SLOPE * v11;
    const int row0 = m0 + rq * 2;
    *(float2*)&C[(size_t)row0 * LDC + col] = make_float2(v00, v01);
    *(float2*)&C[(size_t)(row0 + 1) * LDC + col] = make_float2(v10, v11);
}

#define GEMM_SMEM (16 * 512 * 4 + 2 * 2048 * 4)   // 49152

// ---------------- launch ----------------
extern "C" void kernel_launch(void* const* d_in, const int* in_sizes, int n_in,
                              void* d_out, int out_size) {
    const float* x        = (const float*)d_in[0];
    const int*   ei       = (const int*)d_in[1];
    const float* ea       = (const float*)d_in[2];
    const float* W        = (const float*)d_in[5];
    const float* att_src  = (const float*)d_in[6];
    const float* att_dst  = (const float*)d_in[7];
    const float* W_edge   = (const float*)d_in[8];
    const float* att_edge = (const float*)d_in[9];
    const float* bias     = (const float*)d_in[10];
    const float* fcW      = (const float*)d_in[11];
    const float* fcb      = (const float*)d_in[12];
    float* out = (float*)d_out;
    const int E = in_sizes[1] / 2;
    const int nslab = (E + EPB - 1) / EPB;

    cudaFuncSetAttribute(k_gemm<0>, cudaFuncAttributeMaxDynamicSharedMemorySize, GEMM_SMEM);
    cudaFuncSetAttribute(k_gemm<1>, cudaFuncAttributeMaxDynamicSharedMemorySize, GEMM_SMEM);

    k_prep<<<nslab + 264, 256>>>(ei, ea, W, att_src, att_dst, W_edge, att_edge, E, nslab);
    k_dst<<<NOUT, 256>>>(x, ea, 1.0f / (float)E);
    k_gemm<0><<<(NOUT / 16) * 8, 256, GEMM_SMEM>>>(W, bias, nullptr);
    k_gemm<1><<<(NOUT / 16) * 4, 256, GEMM_SMEM>>>(fcW, fcb, out);
}

// round 15
// speedup vs baseline: 1.5507x; 1.0715x over previous
#include <cuda_runtime.h>
#include <cstdint>
#include <math.h>

// ---------------- problem constants ----------------
#define N_NODES 27648
#define F_IN    256
#define HC      512
#define NHEAD   4
#define DE      16
#define HID     256
#define NA      48
#define NOUT    576
#define CAP     64
#define SLOPE_ATT 0.2f
#define SLOPE     0.01f
#define EPB     512

// ---------------- device scratch ----------------
__device__ float g_wv[F_IN * 8];                // wv[f][j]: j<4 src head, j>=4 dst head
__device__ float g_wattE[DE * NHEAD];
__device__ float g_easum[DE];                   // zero-init; reset by k_gemm<0> each replay
__device__ int   g_dstcnt[NOUT];                // zero-init; reset by k_dst each replay
__device__ int   g_ebsrc[NOUT * CAP];           // src node ids
__device__ int   g_ebeid[NOUT * CAP];           // edge ids
__device__ float g_xagg[NOUT * NHEAD * F_IN];   // per-dst per-head aggregated x
__device__ float g_hact[NOUT * HC];

__device__ __forceinline__ int diag_node(int i) { return (i / NA) * (NA * NA) + (i % NA) * (NA + 1); }

// ================= K1: prep — wv + wattE + easum + scan/bucket ==============
__global__ void __launch_bounds__(256)
k_prep(const int* __restrict__ ei, const float* __restrict__ ea,
       const float* __restrict__ W, const float* __restrict__ att_src,
       const float* __restrict__ att_dst, const float* __restrict__ W_edge,
       const float* __restrict__ att_edge, int E, int nslab)
{
    const int tid = threadIdx.x;
    const int wid = tid >> 5, lane = tid & 31;
    const int bid = blockIdx.x;

    if (bid < nslab) {
        __shared__ float s_ea[DE];
        if (tid < DE) s_ea[tid] = 0.f;
        __syncthreads();
        const int ebase = bid * EPB;
        {
            const float4* ea4 = (const float4*)ea;
            const int g0 = ebase * 4;
            const int lim4 = E * 4;
            float4 acc = make_float4(0.f, 0.f, 0.f, 0.f);
            #pragma unroll
            for (int i = 0; i < EPB * 4 / 256; i++) {
                int g4 = g0 + tid + i * 256;
                if (g4 < lim4) {
                    float4 v = ea4[g4];
                    acc.x += v.x; acc.y += v.y; acc.z += v.z; acc.w += v.w;
                }
            }
            int d0 = (tid & 3) * 4;
            atomicAdd(&s_ea[d0 + 0], acc.x);
            atomicAdd(&s_ea[d0 + 1], acc.y);
            atomicAdd(&s_ea[d0 + 2], acc.z);
            atomicAdd(&s_ea[d0 + 3], acc.w);
        }
        if (tid < EPB / 4) {
            const int* dst = ei + E;
            const int e0 = ebase + tid * 4;
            if (e0 + 3 < E) {
                int4 d4 = *(const int4*)(dst + e0);
                #pragma unroll
                for (int j = 0; j < 4; j++) {
                    int d = (j == 0) ? d4.x : (j == 1) ? d4.y : (j == 2) ? d4.z : d4.w;
                    int rem = d % (NA * NA);
                    if (rem % (NA + 1) == 0) {
                        int e = e0 + j;
                        int dc = (d / (NA * NA)) * NA + rem / (NA + 1);
                        int p = atomicAdd(&g_dstcnt[dc], 1);
                        if (p < CAP) {
                            g_ebsrc[dc * CAP + p] = ei[e];
                            g_ebeid[dc * CAP + p] = e;
                        }
                    }
                }
            } else {
                for (int j = 0; j < 4; j++) {
                    int e = e0 + j;
                    if (e >= E) break;
                    int d = dst[e];
                    int rem = d % (NA * NA);
                    if (rem % (NA + 1) == 0) {
                        int dc = (d / (NA * NA)) * NA + rem / (NA + 1);
                        int p = atomicAdd(&g_dstcnt[dc], 1);
                        if (p < CAP) {
                            g_ebsrc[dc * CAP + p] = ei[e];
                            g_ebeid[dc * CAP + p] = e;
                        }
                    }
                }
            }
        }
        __syncthreads();
        if (tid < DE) atomicAdd(&g_easum[tid], s_ea[tid]);
    } else if (bid < nslab + 256) {
        int pair = (bid - nslab) * 8 + wid;       // < 2048
        int f = pair >> 3, j = pair & 7, h = j & 3;
        const float* att = ((j < 4) ? att_src : att_dst) + h * 128;
        float4 w4 = *(const float4*)(W + (size_t)f * HC + h * 128 + lane * 4);
        float4 a4 = *(const float4*)(att + lane * 4);
        float s = w4.x * a4.x + w4.y * a4.y + w4.z * a4.z + w4.w * a4.w;
        #pragma unroll
        for (int off = 16; off > 0; off >>= 1) s += __shfl_down_sync(0xffffffffu, s, off);
        if (lane == 0) g_wv[f * 8 + j] = s;
    } else {
        int pair = (bid - nslab - 256) * 8 + wid; // < 64
        int d = pair >> 2, h = pair & 3;
        float4 w4 = *(const float4*)(W_edge + (size_t)d * HC + h * 128 + lane * 4);
        float4 a4 = *(const float4*)(att_edge + h * 128 + lane * 4);
        float s = w4.x * a4.x + w4.y * a4.y + w4.z * a4.z + w4.w * a4.w;
        #pragma unroll
        for (int off = 16; off > 0; off >>= 1) s += __shfl_down_sync(0xffffffffu, s, off);
        if (lane == 0) g_wattE[pair] = s;
    }
}

// ================= K2: per-dst scores + softmax + x-aggregation =============
__global__ void __launch_bounds__(256)
k_dst(const float* __restrict__ x, const float* __restrict__ ea, float invE)
{
    const int dc = blockIdx.x;
    const int tid = threadIdx.x;
    const int wid = tid >> 5, lane = tid & 31;
    __shared__ float s_an[(CAP + 1) * 8];
    __shared__ float s_w[(CAP + 1) * NHEAD];
    __shared__ float s_wE[DE * NHEAD];
    __shared__ float s_aloop[NHEAD];
    __shared__ float s_inv[NHEAD];
    __shared__ int   s_sn[CAP + 1];
    __shared__ int   s_eid[CAP];
    __shared__ int   s_cnt;

    if (tid < DE * NHEAD) s_wE[tid] = g_wattE[tid];
    if (tid == 0) {
        int c = g_dstcnt[dc];
        s_cnt = c < CAP ? c : CAP;
        g_dstcnt[dc] = 0;                          // restore for next replay
    }
    __syncthreads();
    if (tid < NHEAD) {
        float a = 0.f;
        #pragma unroll
        for (int d = 0; d < DE; d++) a += g_easum[d] * invE * s_wE[d * NHEAD + tid];
        s_aloop[tid] = a;
    }
    const int cnt = s_cnt;
    const int dn = diag_node(dc);
    if (tid < cnt) {
        s_sn[tid] = g_ebsrc[dc * CAP + tid];
        s_eid[tid] = g_ebeid[dc * CAP + tid];
    } else if (tid == cnt) {
        s_sn[cnt] = dn;                            // self-loop source = dst node
    }
    __syncthreads();
    // sweep1: 8 attention dots per entry (warp per entry)
    for (int ent = wid; ent <= cnt; ent += 8) {
        const float4* xr4 = (const float4*)(x + (size_t)s_sn[ent] * F_IN);
        float4 a4 = xr4[lane * 2];
        float4 b4 = xr4[lane * 2 + 1];
        float xv[8] = {a4.x, a4.y, a4.z, a4.w, b4.x, b4.y, b4.z, b4.w};
        float p[8] = {0.f, 0.f, 0.f, 0.f, 0.f, 0.f, 0.f, 0.f};
        #pragma unroll
        for (int q = 0; q < 8; q++) {
            const float4* wv4 = (const float4*)&g_wv[(lane * 8 + q) * 8];
            float4 w0 = wv4[0], w1 = wv4[1];
            p[0] += xv[q] * w0.x; p[1] += xv[q] * w0.y;
            p[2] += xv[q] * w0.z; p[3] += xv[q] * w0.w;
            p[4] += xv[q] * w1.x; p[5] += xv[q] * w1.y;
            p[6] += xv[q] * w1.z; p[7] += xv[q] * w1.w;
        }
        #pragma unroll
        for (int j = 0; j < 8; j++) {
            float s = p[j];
            #pragma unroll
            for (int off = 16; off > 0; off >>= 1) s += __shfl_down_sync(0xffffffffu, s, off);
            p[j] = s;
        }
        if (lane == 0) {
            *(float4*)&s_an[ent * 8]     = make_float4(p[0], p[1], p[2], p[3]);
            *(float4*)&s_an[ent * 8 + 4] = make_float4(p[4], p[5], p[6], p[7]);
        }
    }
    __syncthreads();
    // logits (+ea-logit recompute, ea L2-hot) -> leaky
    if (tid < cnt) {
        const float4* r = (const float4*)(ea + (size_t)s_eid[tid] * DE);
        float l0 = 0.f, l1 = 0.f, l2 = 0.f, l3 = 0.f;
        #pragma unroll
        for (int q = 0; q < 4; q++) {
            float4 v = r[q];
            const float* w = &s_wE[q * 4 * NHEAD];
            l0 += v.x * w[0] + v.y * w[4] + v.z * w[8]  + v.w * w[12];
            l1 += v.x * w[1] + v.y * w[5] + v.z * w[9]  + v.w * w[13];
            l2 += v.x * w[2] + v.y * w[6] + v.z * w[10] + v.w * w[14];
            l3 += v.x * w[3] + v.y * w[7] + v.z * w[11] + v.w * w[15];
        }
        float le[4] = {l0, l1, l2, l3};
        #pragma unroll
        for (int h = 0; h < NHEAD; h++) {
            float l = s_an[tid * 8 + h] + s_an[cnt * 8 + 4 + h] + le[h];
            s_w[tid * 4 + h] = (l > 0.f) ? l : SLOPE_ATT * l;
        }
    } else if (tid == cnt) {
        #pragma unroll
        for (int h = 0; h < NHEAD; h++) {
            float l = s_an[cnt * 8 + h] + s_an[cnt * 8 + 4 + h] + s_aloop[h];
            s_w[cnt * 4 + h] = (l > 0.f) ? l : SLOPE_ATT * l;
        }
    }
    __syncthreads();
    const int total = cnt + 1;
    if (tid < NHEAD) {
        float m = -3.0e38f;
        for (int e = 0; e < total; e++) m = fmaxf(m, s_w[e * 4 + tid]);
        float su = 0.f;
        for (int e = 0; e < total; e++) { float w = __expf(s_w[e * 4 + tid] - m); s_w[e * 4 + tid] = w; su += w; }
        s_inv[tid] = 1.f / (su + 1e-16f);
    }
    __syncthreads();
    // sweep2: x-space aggregation (x rows L1-hot from sweep1)
    float acc0 = 0.f, acc1 = 0.f, acc2 = 0.f, acc3 = 0.f;
    for (int e = 0; e < total; e++) {
        float xv = x[(size_t)s_sn[e] * F_IN + tid];
        acc0 += s_w[e * 4 + 0] * xv;
        acc1 += s_w[e * 4 + 1] * xv;
        acc2 += s_w[e * 4 + 2] * xv;
        acc3 += s_w[e * 4 + 3] * xv;
    }
    float* xo = &g_xagg[(size_t)dc * NHEAD * F_IN];
    xo[0 * F_IN + tid] = acc0 * s_inv[0];
    xo[1 * F_IN + tid] = acc1 * s_inv[1];
    xo[2 * F_IN + tid] = acc2 * s_inv[2];
    xo[3 * F_IN + tid] = acc3 * s_inv[3];
}

// ================= K3/K4: fully-staged GEMM + bias + leaky ==================
// MODE 0 (gat): C[576,512] = xagg(per-head) @ W,  K=256, 8 col tiles of 64
// MODE 1 (fc) : C[576,256] = hact @ fcW,          K=512, 4 col tiles of 64
// Tile M=16, N=64, all of A and B staged. 256 threads = 64 positions (4x4
// micro-tile) x 4 k-groups; k-group partials reduced via smem (aliases Bs).
template<int MODE>
__global__ void __launch_bounds__(256)
k_gemm(const float* __restrict__ B, const float* __restrict__ bias,
       float* __restrict__ Cext)
{
    constexpr int K    = (MODE == 0) ? 256 : 512;
    constexpr int KQ   = K / 4;                    // per k-group depth
    constexpr int LDA  = (MODE == 0) ? 1024 : 512;
    constexpr int LDB  = (MODE == 0) ? 512 : 256;
    constexpr int LDC  = (MODE == 0) ? 512 : 256;
    constexpr int NCT  = (MODE == 0) ? 8 : 4;
    constexpr int ASTR = K + 4;                    // padded A row stride

    extern __shared__ __align__(16) float sm[];
    float* As = sm;                  // 16 * ASTR
    float* Bs = sm + 16 * ASTR;      // K * 64  (aliased by partials after compute)

    const int tid = threadIdx.x;
    const int bid = blockIdx.x;
    const int m0 = (bid / NCT) * 16;
    const int ct = bid % NCT;
    const int nbase = ct * 64;

    if (MODE == 0 && bid == 0 && tid < DE) g_easum[tid] = 0.f;  // replay restore

    const float* A = (MODE == 0) ? g_xagg : g_hact;
    float* C = (MODE == 0) ? g_hact : Cext;
    const int aoff = (MODE == 0) ? ((ct >> 1) * 256) : 0;

    // stage A: 16 rows x K (float4 both sides)
    #pragma unroll
    for (int i = tid; i < 16 * (K / 4); i += 256) {
        int r = i / (K / 4), k4 = i % (K / 4);
        *(float4*)(As + r * ASTR + k4 * 4) =
            *(const float4*)(A + (size_t)(m0 + r) * LDA + aoff + k4 * 4);
    }
    // stage B: K rows x 64 cols
    #pragma unroll
    for (int i = tid; i < K * 16; i += 256) {
        int row = i >> 4, c4 = i & 15;
        *(float4*)(Bs + row * 64 + c4 * 4) =
            *(const float4*)(B + (size_t)row * LDB + nbase + c4 * 4);
    }
    __syncthreads();

    // compute: kg = tid>>6 (k-quarter), pos = tid&63 -> 4x4 micro-tile
    const int kg = tid >> 6;
    const int pos = tid & 63;
    const int r4 = pos >> 4, c4 = pos & 15;
    const float* Ab = As + (r4 * 4) * ASTR + kg * KQ;
    const float* Bb = Bs + kg * KQ * 64 + c4 * 4;
    float acc[4][4];
    #pragma unroll
    for (int i = 0; i < 4; i++)
        #pragma unroll
        for (int j = 0; j < 4; j++) acc[i][j] = 0.f;

    #pragma unroll 4
    for (int kk = 0; kk < KQ; kk++) {
        float4 b = *(const float4*)(Bb + kk * 64);
        float a0 = Ab[kk];
        float a1 = Ab[ASTR + kk];
        float a2 = Ab[2 * ASTR + kk];
        float a3 = Ab[3 * ASTR + kk];
        acc[0][0] += a0 * b.x; acc[0][1] += a0 * b.y; acc[0][2] += a0 * b.z; acc[0][3] += a0 * b.w;
        acc[1][0] += a1 * b.x; acc[1][1] += a1 * b.y; acc[1][2] += a1 * b.z; acc[1][3] += a1 * b.w;
        acc[2][0] += a2 * b.x; acc[2][1] += a2 * b.y; acc[2][2] += a2 * b.z; acc[2][3] += a2 * b.w;
        acc[3][0] += a3 * b.x; acc[3][1] += a3 * b.y; acc[3][2] += a3 * b.z; acc[3][3] += a3 * b.w;
    }
    __syncthreads();

    // write k-group partials into Bs alias: part[kg][r][64]
    float* part = Bs;
    #pragma unroll
    for (int i = 0; i < 4; i++)
        *(float4*)(part + kg * 1024 + (r4 * 4 + i) * 64 + c4 * 4) =
            make_float4(acc[i][0], acc[i][1], acc[i][2], acc[i][3]);
    __syncthreads();

    // reduce 4 k-groups + bias + leaky + store (thread -> 4 consecutive outputs)
    {
        const int o = tid * 4;
        const int r = o >> 6, c = o & 63;
        float4 s0 = *(const float4*)(part + o);
        float4 s1 = *(const float4*)(part + 1024 + o);
        float4 s2 = *(const float4*)(part + 2048 + o);
        float4 s3 = *(const float4*)(part + 3072 + o);
        float4 b4 = *(const float4*)(bias + nbase + c);
        float4 v;
        v.x = s0.x + s1.x + s2.x + s3.x + b4.x;
        v.y = s0.y + s1.y + s2.y + s3.y + b4.y;
        v.z = s0.z + s1.z + s2.z + s3.z + b4.z;
        v.w = s0.w + s1.w + s2.w + s3.w + b4.w;
        v.x = (v.x > 0.f) ? v.x : SLOPE * v.x;
        v.y = (v.y > 0.f) ? v.y : SLOPE * v.y;
        v.z = (v.z > 0.f) ? v.z : SLOPE * v.z;
        v.w = (v.w > 0.f) ? v.w : SLOPE * v.w;
        *(float4*)&C[(size_t)(m0 + r) * LDC + nbase + c] = v;
    }
}

#define GEMM0_SMEM ((16 * (256 + 4) + 256 * 64) * 4)   //  82,176 B
#define GEMM1_SMEM ((16 * (512 + 4) + 512 * 64) * 4)   // 164,096 B

// ---------------- launch ----------------
extern "C" void kernel_launch(void* const* d_in, const int* in_sizes, int n_in,
                              void* d_out, int out_size) {
    const float* x        = (const float*)d_in[0];
    const int*   ei       = (const int*)d_in[1];
    const float* ea       = (const float*)d_in[2];
    const float* W        = (const float*)d_in[5];
    const float* att_src  = (const float*)d_in[6];
    const float* att_dst  = (const float*)d_in[7];
    const float* W_edge   = (const float*)d_in[8];
    const float* att_edge = (const float*)d_in[9];
    const float* bias     = (const float*)d_in[10];
    const float* fcW      = (const float*)d_in[11];
    const float* fcb      = (const float*)d_in[12];
    float* out = (float*)d_out;
    const int E = in_sizes[1] / 2;
    const int nslab = (E + EPB - 1) / EPB;

    cudaFuncSetAttribute(k_gemm<0>, cudaFuncAttributeMaxDynamicSharedMemorySize, GEMM0_SMEM);
    cudaFuncSetAttribute(k_gemm<1>, cudaFuncAttributeMaxDynamicSharedMemorySize, GEMM1_SMEM);

    k_prep<<<nslab + 264, 256>>>(ei, ea, W, att_src, att_dst, W_edge, att_edge, E, nslab);
    k_dst<<<NOUT, 256>>>(x, ea, 1.0f / (float)E);
    k_gemm<0><<<(NOUT / 16) * 8, 256, GEMM0_SMEM>>>(W, bias, nullptr);
    k_gemm<1><<<(NOUT / 16) * 4, 256, GEMM1_SMEM>>>(fcW, fcb, out);
}

// round 16
// speedup vs baseline: 1.5902x; 1.0255x over previous
#include <cuda_runtime.h>
#include <cstdint>
#include <math.h>

// ---------------- problem constants ----------------
#define N_NODES 27648
#define F_IN    256
#define HC      512
#define NHEAD   4
#define DE      16
#define HID     256
#define NA      48
#define NOUT    576
#define CAP     64
#define SLOPE_ATT 0.2f
#define SLOPE     0.01f
#define EPB     512

// ---------------- device scratch ----------------
__device__ float g_wv[F_IN * 8];                // wv[f][j]: j<4 src head, j>=4 dst head
__device__ float g_wattE[DE * NHEAD];
__device__ float g_easum[DE];                   // zero-init; reset by k_gemm<0> each replay
__device__ int   g_dstcnt[NOUT];                // zero-init; reset by k_dst each replay
__device__ int   g_ebsrc[NOUT * CAP];           // src node ids
__device__ int   g_ebeid[NOUT * CAP];           // edge ids
__device__ float g_xagg[NOUT * NHEAD * F_IN];   // per-dst per-head aggregated x
__device__ float g_hact[NOUT * HC];

__device__ __forceinline__ int diag_node(int i) { return (i / NA) * (NA * NA) + (i % NA) * (NA + 1); }

// ================= K1: prep — wv + wattE + easum + scan/bucket ==============
__global__ void __launch_bounds__(256)
k_prep(const int* __restrict__ ei, const float* __restrict__ ea,
       const float* __restrict__ W, const float* __restrict__ att_src,
       const float* __restrict__ att_dst, const float* __restrict__ W_edge,
       const float* __restrict__ att_edge, int E, int nslab)
{
    const int tid = threadIdx.x;
    const int wid = tid >> 5, lane = tid & 31;
    const int bid = blockIdx.x;

    if (bid < nslab) {
        __shared__ float s_ea[DE];
        if (tid < DE) s_ea[tid] = 0.f;
        __syncthreads();
        const int ebase = bid * EPB;
        {
            const float4* ea4 = (const float4*)ea;
            const int g0 = ebase * 4;
            const int lim4 = E * 4;
            float4 acc = make_float4(0.f, 0.f, 0.f, 0.f);
            #pragma unroll
            for (int i = 0; i < EPB * 4 / 256; i++) {
                int g4 = g0 + tid + i * 256;
                if (g4 < lim4) {
                    float4 v = ea4[g4];
                    acc.x += v.x; acc.y += v.y; acc.z += v.z; acc.w += v.w;
                }
            }
            int d0 = (tid & 3) * 4;
            atomicAdd(&s_ea[d0 + 0], acc.x);
            atomicAdd(&s_ea[d0 + 1], acc.y);
            atomicAdd(&s_ea[d0 + 2], acc.z);
            atomicAdd(&s_ea[d0 + 3], acc.w);
        }
        if (tid < EPB / 4) {
            const int* dst = ei + E;
            const int e0 = ebase + tid * 4;
            if (e0 + 3 < E) {
                int4 d4 = *(const int4*)(dst + e0);
                #pragma unroll
                for (int j = 0; j < 4; j++) {
                    int d = (j == 0) ? d4.x : (j == 1) ? d4.y : (j == 2) ? d4.z : d4.w;
                    int rem = d % (NA * NA);
                    if (rem % (NA + 1) == 0) {
                        int e = e0 + j;
                        int dc = (d / (NA * NA)) * NA + rem / (NA + 1);
                        int p = atomicAdd(&g_dstcnt[dc], 1);
                        if (p < CAP) {
                            g_ebsrc[dc * CAP + p] = ei[e];
                            g_ebeid[dc * CAP + p] = e;
                        }
                    }
                }
            } else {
                for (int j = 0; j < 4; j++) {
                    int e = e0 + j;
                    if (e >= E) break;
                    int d = dst[e];
                    int rem = d % (NA * NA);
                    if (rem % (NA + 1) == 0) {
                        int dc = (d / (NA * NA)) * NA + rem / (NA + 1);
                        int p = atomicAdd(&g_dstcnt[dc], 1);
                        if (p < CAP) {
                            g_ebsrc[dc * CAP + p] = ei[e];
                            g_ebeid[dc * CAP + p] = e;
                        }
                    }
                }
            }
        }
        __syncthreads();
        if (tid < DE) atomicAdd(&g_easum[tid], s_ea[tid]);
    } else if (bid < nslab + 256) {
        int pair = (bid - nslab) * 8 + wid;       // < 2048
        int f = pair >> 3, j = pair & 7, h = j & 3;
        const float* att = ((j < 4) ? att_src : att_dst) + h * 128;
        float4 w4 = *(const float4*)(W + (size_t)f * HC + h * 128 + lane * 4);
        float4 a4 = *(const float4*)(att + lane * 4);
        float s = w4.x * a4.x + w4.y * a4.y + w4.z * a4.z + w4.w * a4.w;
        #pragma unroll
        for (int off = 16; off > 0; off >>= 1) s += __shfl_down_sync(0xffffffffu, s, off);
        if (lane == 0) g_wv[f * 8 + j] = s;
    } else {
        int pair = (bid - nslab - 256) * 8 + wid; // < 64
        int d = pair >> 2, h = pair & 3;
        float4 w4 = *(const float4*)(W_edge + (size_t)d * HC + h * 128 + lane * 4);
        float4 a4 = *(const float4*)(att_edge + h * 128 + lane * 4);
        float s = w4.x * a4.x + w4.y * a4.y + w4.z * a4.z + w4.w * a4.w;
        #pragma unroll
        for (int off = 16; off > 0; off >>= 1) s += __shfl_down_sync(0xffffffffu, s, off);
        if (lane == 0) g_wattE[pair] = s;
    }
}

// ================= K2: per-dst scores + softmax + x-aggregation =============
__global__ void __launch_bounds__(256)
k_dst(const float* __restrict__ x, const float* __restrict__ ea, float invE)
{
    const int dc = blockIdx.x;
    const int tid = threadIdx.x;
    const int wid = tid >> 5, lane = tid & 31;
    __shared__ float s_an[(CAP + 1) * 8];
    __shared__ float s_w[(CAP + 1) * NHEAD];
    __shared__ float s_wE[DE * NHEAD];
    __shared__ float s_aloop[NHEAD];
    __shared__ float s_inv[NHEAD];
    __shared__ int   s_sn[CAP + 1];
    __shared__ int   s_eid[CAP];
    __shared__ int   s_cnt;

    if (tid < DE * NHEAD) s_wE[tid] = g_wattE[tid];
    if (tid == 0) {
        int c = g_dstcnt[dc];
        s_cnt = c < CAP ? c : CAP;
        g_dstcnt[dc] = 0;                          // restore for next replay
    }
    __syncthreads();
    if (tid < NHEAD) {
        float a = 0.f;
        #pragma unroll
        for (int d = 0; d < DE; d++) a += g_easum[d] * invE * s_wE[d * NHEAD + tid];
        s_aloop[tid] = a;
    }
    const int cnt = s_cnt;
    const int dn = diag_node(dc);
    if (tid < cnt) {
        s_sn[tid] = g_ebsrc[dc * CAP + tid];
        s_eid[tid] = g_ebeid[dc * CAP + tid];
    } else if (tid == cnt) {
        s_sn[cnt] = dn;                            // self-loop source = dst node
    }
    __syncthreads();
    // sweep1: 8 attention dots per entry (warp per entry)
    for (int ent = wid; ent <= cnt; ent += 8) {
        const float4* xr4 = (const float4*)(x + (size_t)s_sn[ent] * F_IN);
        float4 a4 = xr4[lane * 2];
        float4 b4 = xr4[lane * 2 + 1];
        float xv[8] = {a4.x, a4.y, a4.z, a4.w, b4.x, b4.y, b4.z, b4.w};
        float p[8] = {0.f, 0.f, 0.f, 0.f, 0.f, 0.f, 0.f, 0.f};
        #pragma unroll
        for (int q = 0; q < 8; q++) {
            const float4* wv4 = (const float4*)&g_wv[(lane * 8 + q) * 8];
            float4 w0 = wv4[0], w1 = wv4[1];
            p[0] += xv[q] * w0.x; p[1] += xv[q] * w0.y;
            p[2] += xv[q] * w0.z; p[3] += xv[q] * w0.w;
            p[4] += xv[q] * w1.x; p[5] += xv[q] * w1.y;
            p[6] += xv[q] * w1.z; p[7] += xv[q] * w1.w;
        }
        #pragma unroll
        for (int j = 0; j < 8; j++) {
            float s = p[j];
            #pragma unroll
            for (int off = 16; off > 0; off >>= 1) s += __shfl_down_sync(0xffffffffu, s, off);
            p[j] = s;
        }
        if (lane == 0) {
            *(float4*)&s_an[ent * 8]     = make_float4(p[0], p[1], p[2], p[3]);
            *(float4*)&s_an[ent * 8 + 4] = make_float4(p[4], p[5], p[6], p[7]);
        }
    }
    __syncthreads();
    // logits (+ea-logit recompute, ea L2-hot) -> leaky
    if (tid < cnt) {
        const float4* r = (const float4*)(ea + (size_t)s_eid[tid] * DE);
        float l0 = 0.f, l1 = 0.f, l2 = 0.f, l3 = 0.f;
        #pragma unroll
        for (int q = 0; q < 4; q++) {
            float4 v = r[q];
            const float* w = &s_wE[q * 4 * NHEAD];
            l0 += v.x * w[0] + v.y * w[4] + v.z * w[8]  + v.w * w[12];
            l1 += v.x * w[1] + v.y * w[5] + v.z * w[9]  + v.w * w[13];
            l2 += v.x * w[2] + v.y * w[6] + v.z * w[10] + v.w * w[14];
            l3 += v.x * w[3] + v.y * w[7] + v.z * w[11] + v.w * w[15];
        }
        float le[4] = {l0, l1, l2, l3};
        #pragma unroll
        for (int h = 0; h < NHEAD; h++) {
            float l = s_an[tid * 8 + h] + s_an[cnt * 8 + 4 + h] + le[h];
            s_w[tid * 4 + h] = (l > 0.f) ? l : SLOPE_ATT * l;
        }
    } else if (tid == cnt) {
        #pragma unroll
        for (int h = 0; h < NHEAD; h++) {
            float l = s_an[cnt * 8 + h] + s_an[cnt * 8 + 4 + h] + s_aloop[h];
            s_w[cnt * 4 + h] = (l > 0.f) ? l : SLOPE_ATT * l;
        }
    }
    __syncthreads();
    const int total = cnt + 1;
    if (tid < NHEAD) {
        float m = -3.0e38f;
        for (int e = 0; e < total; e++) m = fmaxf(m, s_w[e * 4 + tid]);
        float su = 0.f;
        for (int e = 0; e < total; e++) { float w = __expf(s_w[e * 4 + tid] - m); s_w[e * 4 + tid] = w; su += w; }
        s_inv[tid] = 1.f / (su + 1e-16f);
    }
    __syncthreads();
    // sweep2: x-space aggregation (x rows L1-hot from sweep1)
    float acc0 = 0.f, acc1 = 0.f, acc2 = 0.f, acc3 = 0.f;
    for (int e = 0; e < total; e++) {
        float xv = x[(size_t)s_sn[e] * F_IN + tid];
        acc0 += s_w[e * 4 + 0] * xv;
        acc1 += s_w[e * 4 + 1] * xv;
        acc2 += s_w[e * 4 + 2] * xv;
        acc3 += s_w[e * 4 + 3] * xv;
    }
    float* xo = &g_xagg[(size_t)dc * NHEAD * F_IN];
    xo[0 * F_IN + tid] = acc0 * s_inv[0];
    xo[1 * F_IN + tid] = acc1 * s_inv[1];
    xo[2 * F_IN + tid] = acc2 * s_inv[2];
    xo[3 * F_IN + tid] = acc3 * s_inv[3];
}

// ================= K3/K4: fully-staged GEMM + bias + leaky ==================
// MODE 0 (gat): C[576,512] = xagg(per-head) @ W,  K=256, 16 col tiles of 32
// MODE 1 (fc) : C[576,256] = hact @ fcW,          K=512,  8 col tiles of 32
// Tile M=16, N=32. 256 threads = 8 warps; warp = k-group (K/8 each),
// 32 positions/warp = 4 rows x 8 col-quads (4x4 micro-tile).
// Partials for 8 k-groups reduced via smem alias of Bs.
template<int MODE>
__global__ void __launch_bounds__(256)
k_gemm(const float* __restrict__ B, const float* __restrict__ bias,
       float* __restrict__ Cext)
{
    constexpr int K    = (MODE == 0) ? 256 : 512;
    constexpr int KQ   = K / 8;                    // per k-group depth
    constexpr int LDA  = (MODE == 0) ? 1024 : 512;
    constexpr int LDB  = (MODE == 0) ? 512 : 256;
    constexpr int LDC  = (MODE == 0) ? 512 : 256;
    constexpr int NCT  = (MODE == 0) ? 16 : 8;
    constexpr int ASTR = K + 4;                    // padded A row stride

    extern __shared__ __align__(16) float sm[];
    float* As = sm;                  // 16 * ASTR
    float* Bs = sm + 16 * ASTR;      // K * 32  (aliased by partials after compute)

    const int tid = threadIdx.x;
    const int bid = blockIdx.x;
    const int m0 = (bid / NCT) * 16;
    const int ct = bid % NCT;
    const int nbase = ct * 32;

    if (MODE == 0 && bid == 0 && tid < DE) g_easum[tid] = 0.f;  // replay restore

    const float* A = (MODE == 0) ? g_xagg : g_hact;
    float* C = (MODE == 0) ? g_hact : Cext;
    const int aoff = (MODE == 0) ? ((ct >> 2) * 256) : 0;   // head = ct/4

    // stage A: 16 rows x K
    #pragma unroll
    for (int i = tid; i < 16 * (K / 4); i += 256) {
        int r = i / (K / 4), k4 = i % (K / 4);
        *(float4*)(As + r * ASTR + k4 * 4) =
            *(const float4*)(A + (size_t)(m0 + r) * LDA + aoff + k4 * 4);
    }
    // stage B: K rows x 32 cols
    #pragma unroll
    for (int i = tid; i < K * 8; i += 256) {
        int row = i >> 3, c4 = i & 7;
        *(float4*)(Bs + row * 32 + c4 * 4) =
            *(const float4*)(B + (size_t)row * LDB + nbase + c4 * 4);
    }
    __syncthreads();

    // compute: warp = k-group; pos = lane: r4 = lane>>3 (0..3), c8 = lane&7
    const int kg = tid >> 5;
    const int lane = tid & 31;
    const int r4 = lane >> 3, c8 = lane & 7;
    const float* Ab = As + (r4 * 4) * ASTR + kg * KQ;
    const float* Bb = Bs + kg * KQ * 32 + c8 * 4;
    float acc[4][4];
    #pragma unroll
    for (int i = 0; i < 4; i++)
        #pragma unroll
        for (int j = 0; j < 4; j++) acc[i][j] = 0.f;

    #pragma unroll 8
    for (int kk = 0; kk < KQ; kk++) {
        float4 b = *(const float4*)(Bb + kk * 32);
        float a0 = Ab[kk];
        float a1 = Ab[ASTR + kk];
        float a2 = Ab[2 * ASTR + kk];
        float a3 = Ab[3 * ASTR + kk];
        acc[0][0] += a0 * b.x; acc[0][1] += a0 * b.y; acc[0][2] += a0 * b.z; acc[0][3] += a0 * b.w;
        acc[1][0] += a1 * b.x; acc[1][1] += a1 * b.y; acc[1][2] += a1 * b.z; acc[1][3] += a1 * b.w;
        acc[2][0] += a2 * b.x; acc[2][1] += a2 * b.y; acc[2][2] += a2 * b.z; acc[2][3] += a2 * b.w;
        acc[3][0] += a3 * b.x; acc[3][1] += a3 * b.y; acc[3][2] += a3 * b.z; acc[3][3] += a3 * b.w;
    }
    __syncthreads();

    // write k-group partials into Bs alias: part[kg][16][32]
    float* part = Bs;
    #pragma unroll
    for (int i = 0; i < 4; i++)
        *(float4*)(part + kg * 512 + (r4 * 4 + i) * 32 + c8 * 4) =
            make_float4(acc[i][0], acc[i][1], acc[i][2], acc[i][3]);
    __syncthreads();

    // reduce 8 k-groups + bias + leaky + store (thread -> 2 consecutive outputs)
    {
        const int o = tid * 2;
        const int r = o >> 5, c = o & 31;
        float2 s = *(const float2*)(part + o);
        #pragma unroll
        for (int q = 1; q < 8; q++) {
            float2 t = *(const float2*)(part + q * 512 + o);
            s.x += t.x; s.y += t.y;
        }
        float2 b2 = *(const float2*)(bias + nbase + c);
        float vx = s.x + b2.x, vy = s.y + b2.y;
        vx = (vx > 0.f) ? vx : SLOPE * vx;
        vy = (vy > 0.f) ? vy : SLOPE * vy;
        *(float2*)&C[(size_t)(m0 + r) * LDC + nbase + c] = make_float2(vx, vy);
    }
}

#define GEMM0_SMEM ((16 * (256 + 4) + 256 * 32) * 4)   // 49,408 B
#define GEMM1_SMEM ((16 * (512 + 4) + 512 * 32) * 4)   // 98,560 B

// ---------------- launch ----------------
extern "C" void kernel_launch(void* const* d_in, const int* in_sizes, int n_in,
                              void* d_out, int out_size) {
    const float* x        = (const float*)d_in[0];
    const int*   ei       = (const int*)d_in[1];
    const float* ea       = (const float*)d_in[2];
    const float* W        = (const float*)d_in[5];
    const float* att_src  = (const float*)d_in[6];
    const float* att_dst  = (const float*)d_in[7];
    const float* W_edge   = (const float*)d_in[8];
    const float* att_edge = (const float*)d_in[9];
    const float* bias     = (const float*)d_in[10];
    const float* fcW      = (const float*)d_in[11];
    const float* fcb      = (const float*)d_in[12];
    float* out = (float*)d_out;
    const int E = in_sizes[1] / 2;
    const int nslab = (E + EPB - 1) / EPB;

    cudaFuncSetAttribute(k_gemm<0>, cudaFuncAttributeMaxDynamicSharedMemorySize, GEMM0_SMEM);
    cudaFuncSetAttribute(k_gemm<1>, cudaFuncAttributeMaxDynamicSharedMemorySize, GEMM1_SMEM);

    k_prep<<<nslab + 264, 256>>>(ei, ea, W, att_src, att_dst, W_edge, att_edge, E, nslab);
    k_dst<<<NOUT, 256>>>(x, ea, 1.0f / (float)E);
    k_gemm<0><<<(NOUT / 16) * 16, 256, GEMM0_SMEM>>>(W, bias, nullptr);
    k_gemm<1><<<(NOUT / 16) * 8, 256, GEMM1_SMEM>>>(fcW, fcb, out);
}

// round 17
// speedup vs baseline: 1.6344x; 1.0278x over previous
#include <cuda_runtime.h>
#include <cstdint>
#include <math.h>

// ---------------- problem constants ----------------
#define N_NODES 27648
#define F_IN    256
#define HC      512
#define NHEAD   4
#define DE      16
#define HID     256
#define NA      48
#define NOUT    576
#define CAP     64
#define SLOPE_ATT 0.2f
#define SLOPE     0.01f
#define EPB     512

// ---------------- device scratch ----------------
__device__ float g_wv[F_IN * 8];                // wv[f][j]: j<4 src head, j>=4 dst head
__device__ float g_wattE[DE * NHEAD];
__device__ float g_easum[DE];                   // zero-init; reset by k_gemm<0> each replay
__device__ int   g_dstcnt[NOUT];                // zero-init; reset by k_dst each replay
__device__ int   g_ebsrc[NOUT * CAP];           // src node ids
__device__ int   g_ebeid[NOUT * CAP];           // edge ids
__device__ float g_xagg[NOUT * NHEAD * F_IN];   // per-dst per-head aggregated x
__device__ float g_hact[NOUT * HC];

__device__ __forceinline__ int diag_node(int i) { return (i / NA) * (NA * NA) + (i % NA) * (NA + 1); }

// ================= K1: prep — wv + wattE + easum + scan/bucket ==============
__global__ void __launch_bounds__(256)
k_prep(const int* __restrict__ ei, const float* __restrict__ ea,
       const float* __restrict__ W, const float* __restrict__ att_src,
       const float* __restrict__ att_dst, const float* __restrict__ W_edge,
       const float* __restrict__ att_edge, int E, int nslab)
{
    const int tid = threadIdx.x;
    const int wid = tid >> 5, lane = tid & 31;
    const int bid = blockIdx.x;

    if (bid < nslab) {
        __shared__ float s_ea[DE];
        if (tid < DE) s_ea[tid] = 0.f;
        __syncthreads();
        const int ebase = bid * EPB;
        {
            const float4* ea4 = (const float4*)ea;
            const int g0 = ebase * 4;
            const int lim4 = E * 4;
            float4 acc = make_float4(0.f, 0.f, 0.f, 0.f);
            #pragma unroll
            for (int i = 0; i < EPB * 4 / 256; i++) {
                int g4 = g0 + tid + i * 256;
                if (g4 < lim4) {
                    float4 v = ea4[g4];
                    acc.x += v.x; acc.y += v.y; acc.z += v.z; acc.w += v.w;
                }
            }
            int d0 = (tid & 3) * 4;
            atomicAdd(&s_ea[d0 + 0], acc.x);
            atomicAdd(&s_ea[d0 + 1], acc.y);
            atomicAdd(&s_ea[d0 + 2], acc.z);
            atomicAdd(&s_ea[d0 + 3], acc.w);
        }
        if (tid < EPB / 4) {
            const int* dst = ei + E;
            const int e0 = ebase + tid * 4;
            if (e0 + 3 < E) {
                int4 d4 = *(const int4*)(dst + e0);
                #pragma unroll
                for (int j = 0; j < 4; j++) {
                    int d = (j == 0) ? d4.x : (j == 1) ? d4.y : (j == 2) ? d4.z : d4.w;
                    int rem = d % (NA * NA);
                    if (rem % (NA + 1) == 0) {
                        int e = e0 + j;
                        int dc = (d / (NA * NA)) * NA + rem / (NA + 1);
                        int p = atomicAdd(&g_dstcnt[dc], 1);
                        if (p < CAP) {
                            g_ebsrc[dc * CAP + p] = ei[e];
                            g_ebeid[dc * CAP + p] = e;
                        }
                    }
                }
            } else {
                for (int j = 0; j < 4; j++) {
                    int e = e0 + j;
                    if (e >= E) break;
                    int d = dst[e];
                    int rem = d % (NA * NA);
                    if (rem % (NA + 1) == 0) {
                        int dc = (d / (NA * NA)) * NA + rem / (NA + 1);
                        int p = atomicAdd(&g_dstcnt[dc], 1);
                        if (p < CAP) {
                            g_ebsrc[dc * CAP + p] = ei[e];
                            g_ebeid[dc * CAP + p] = e;
                        }
                    }
                }
            }
        }
        __syncthreads();
        if (tid < DE) atomicAdd(&g_easum[tid], s_ea[tid]);
    } else if (bid < nslab + 256) {
        int pair = (bid - nslab) * 8 + wid;       // < 2048
        int f = pair >> 3, j = pair & 7, h = j & 3;
        const float* att = ((j < 4) ? att_src : att_dst) + h * 128;
        float4 w4 = *(const float4*)(W + (size_t)f * HC + h * 128 + lane * 4);
        float4 a4 = *(const float4*)(att + lane * 4);
        float s = w4.x * a4.x + w4.y * a4.y + w4.z * a4.z + w4.w * a4.w;
        #pragma unroll
        for (int off = 16; off > 0; off >>= 1) s += __shfl_down_sync(0xffffffffu, s, off);
        if (lane == 0) g_wv[f * 8 + j] = s;
    } else {
        int pair = (bid - nslab - 256) * 8 + wid; // < 64
        int d = pair >> 2, h = pair & 3;
        float4 w4 = *(const float4*)(W_edge + (size_t)d * HC + h * 128 + lane * 4);
        float4 a4 = *(const float4*)(att_edge + h * 128 + lane * 4);
        float s = w4.x * a4.x + w4.y * a4.y + w4.z * a4.z + w4.w * a4.w;
        #pragma unroll
        for (int off = 16; off > 0; off >>= 1) s += __shfl_down_sync(0xffffffffu, s, off);
        if (lane == 0) g_wattE[pair] = s;
    }
}

// ================= K2: per-dst scores + softmax + x-aggregation =============
__global__ void __launch_bounds__(256)
k_dst(const float* __restrict__ x, const float* __restrict__ ea, float invE)
{
    const int dc = blockIdx.x;
    const int tid = threadIdx.x;
    const int wid = tid >> 5, lane = tid & 31;
    __shared__ float s_an[(CAP + 1) * 8];
    __shared__ float s_w[(CAP + 1) * NHEAD];
    __shared__ float s_wE[DE * NHEAD];
    __shared__ float s_aloop[NHEAD];
    __shared__ float s_inv[NHEAD];
    __shared__ int   s_sn[CAP + 1];
    __shared__ int   s_eid[CAP];
    __shared__ int   s_cnt;

#if __CUDA_ARCH__ >= 900
    cudaGridDependencySynchronize();     // PDL: wait for k_prep
#endif

    if (tid < DE * NHEAD) s_wE[tid] = g_wattE[tid];
    if (tid == 0) {
        int c = g_dstcnt[dc];
        s_cnt = c < CAP ? c : CAP;
        g_dstcnt[dc] = 0;                          // restore for next replay
    }
    __syncthreads();
    if (tid < NHEAD) {
        float a = 0.f;
        #pragma unroll
        for (int d = 0; d < DE; d++) a += g_easum[d] * invE * s_wE[d * NHEAD + tid];
        s_aloop[tid] = a;
    }
    const int cnt = s_cnt;
    const int dn = diag_node(dc);
    if (tid < cnt) {
        s_sn[tid] = g_ebsrc[dc * CAP + tid];
        s_eid[tid] = g_ebeid[dc * CAP + tid];
    } else if (tid == cnt) {
        s_sn[cnt] = dn;                            // self-loop source = dst node
    }
    __syncthreads();
    // sweep1: 8 attention dots per entry (warp per entry)
    for (int ent = wid; ent <= cnt; ent += 8) {
        const float4* xr4 = (const float4*)(x + (size_t)s_sn[ent] * F_IN);
        float4 a4 = xr4[lane * 2];
        float4 b4 = xr4[lane * 2 + 1];
        float xv[8] = {a4.x, a4.y, a4.z, a4.w, b4.x, b4.y, b4.z, b4.w};
        float p[8] = {0.f, 0.f, 0.f, 0.f, 0.f, 0.f, 0.f, 0.f};
        #pragma unroll
        for (int q = 0; q < 8; q++) {
            const float4* wv4 = (const float4*)&g_wv[(lane * 8 + q) * 8];
            float4 w0 = wv4[0], w1 = wv4[1];
            p[0] += xv[q] * w0.x; p[1] += xv[q] * w0.y;
            p[2] += xv[q] * w0.z; p[3] += xv[q] * w0.w;
            p[4] += xv[q] * w1.x; p[5] += xv[q] * w1.y;
            p[6] += xv[q] * w1.z; p[7] += xv[q] * w1.w;
        }
        #pragma unroll
        for (int j = 0; j < 8; j++) {
            float s = p[j];
            #pragma unroll
            for (int off = 16; off > 0; off >>= 1) s += __shfl_down_sync(0xffffffffu, s, off);
            p[j] = s;
        }
        if (lane == 0) {
            *(float4*)&s_an[ent * 8]     = make_float4(p[0], p[1], p[2], p[3]);
            *(float4*)&s_an[ent * 8 + 4] = make_float4(p[4], p[5], p[6], p[7]);
        }
    }
    __syncthreads();
    // logits (+ea-logit recompute, ea L2-hot) -> leaky
    if (tid < cnt) {
        const float4* r = (const float4*)(ea + (size_t)s_eid[tid] * DE);
        float l0 = 0.f, l1 = 0.f, l2 = 0.f, l3 = 0.f;
        #pragma unroll
        for (int q = 0; q < 4; q++) {
            float4 v = r[q];
            const float* w = &s_wE[q * 4 * NHEAD];
            l0 += v.x * w[0] + v.y * w[4] + v.z * w[8]  + v.w * w[12];
            l1 += v.x * w[1] + v.y * w[5] + v.z * w[9]  + v.w * w[13];
            l2 += v.x * w[2] + v.y * w[6] + v.z * w[10] + v.w * w[14];
            l3 += v.x * w[3] + v.y * w[7] + v.z * w[11] + v.w * w[15];
        }
        float le[4] = {l0, l1, l2, l3};
        #pragma unroll
        for (int h = 0; h < NHEAD; h++) {
            float l = s_an[tid * 8 + h] + s_an[cnt * 8 + 4 + h] + le[h];
            s_w[tid * 4 + h] = (l > 0.f) ? l : SLOPE_ATT * l;
        }
    } else if (tid == cnt) {
        #pragma unroll
        for (int h = 0; h < NHEAD; h++) {
            float l = s_an[cnt * 8 + h] + s_an[cnt * 8 + 4 + h] + s_aloop[h];
            s_w[cnt * 4 + h] = (l > 0.f) ? l : SLOPE_ATT * l;
        }
    }
    __syncthreads();
    const int total = cnt + 1;
    if (tid < NHEAD) {
        float m = -3.0e38f;
        for (int e = 0; e < total; e++) m = fmaxf(m, s_w[e * 4 + tid]);
        float su = 0.f;
        for (int e = 0; e < total; e++) { float w = __expf(s_w[e * 4 + tid] - m); s_w[e * 4 + tid] = w; su += w; }
        s_inv[tid] = 1.f / (su + 1e-16f);
    }
    __syncthreads();
    // sweep2: x-space aggregation, unrolled x2 for MLP
    float acc0 = 0.f, acc1 = 0.f, acc2 = 0.f, acc3 = 0.f;
    int e = 0;
    for (; e + 1 < total; e += 2) {
        float xa = x[(size_t)s_sn[e] * F_IN + tid];
        float xb = x[(size_t)s_sn[e + 1] * F_IN + tid];
        const float* wa = &s_w[e * 4];
        const float* wb = &s_w[(e + 1) * 4];
        acc0 += wa[0] * xa + wb[0] * xb;
        acc1 += wa[1] * xa + wb[1] * xb;
        acc2 += wa[2] * xa + wb[2] * xb;
        acc3 += wa[3] * xa + wb[3] * xb;
    }
    if (e < total) {
        float xa = x[(size_t)s_sn[e] * F_IN + tid];
        const float* wa = &s_w[e * 4];
        acc0 += wa[0] * xa; acc1 += wa[1] * xa;
        acc2 += wa[2] * xa; acc3 += wa[3] * xa;
    }
    float* xo = &g_xagg[(size_t)dc * NHEAD * F_IN];
    xo[0 * F_IN + tid] = acc0 * s_inv[0];
    xo[1 * F_IN + tid] = acc1 * s_inv[1];
    xo[2 * F_IN + tid] = acc2 * s_inv[2];
    xo[3 * F_IN + tid] = acc3 * s_inv[3];
}

// ================= K3/K4: fully-staged GEMM + bias + leaky ==================
// MODE 0 (gat): C[576,512] = xagg(per-head) @ W,  K=256, 16 col tiles of 32
// MODE 1 (fc) : C[576,256] = hact @ fcW,          K=512,  8 col tiles of 32
// PDL: B (weights, independent of predecessor) staged BEFORE gridsync.
template<int MODE>
__global__ void __launch_bounds__(256)
k_gemm(const float* __restrict__ B, const float* __restrict__ bias,
       float* __restrict__ Cext)
{
    constexpr int K    = (MODE == 0) ? 256 : 512;
    constexpr int KQ   = K / 8;                    // per k-group depth
    constexpr int LDA  = (MODE == 0) ? 1024 : 512;
    constexpr int LDB  = (MODE == 0) ? 512 : 256;
    constexpr int LDC  = (MODE == 0) ? 512 : 256;
    constexpr int NCT  = (MODE == 0) ? 16 : 8;
    constexpr int ASTR = K + 4;                    // padded A row stride

    extern __shared__ __align__(16) float sm[];
    float* As = sm;                  // 16 * ASTR
    float* Bs = sm + 16 * ASTR;      // K * 32  (aliased by partials after compute)

    const int tid = threadIdx.x;
    const int bid = blockIdx.x;
    const int m0 = (bid / NCT) * 16;
    const int ct = bid % NCT;
    const int nbase = ct * 32;

    // ---- pre-sync prologue: stage B (kernel input, independent) ----
    #pragma unroll
    for (int i = tid; i < K * 8; i += 256) {
        int row = i >> 3, c4 = i & 7;
        *(float4*)(Bs + row * 32 + c4 * 4) =
            *(const float4*)(B + (size_t)row * LDB + nbase + c4 * 4);
    }

#if __CUDA_ARCH__ >= 900
    cudaGridDependencySynchronize();     // PDL: wait for predecessor kernel
#endif

    if (MODE == 0 && bid == 0 && tid < DE) g_easum[tid] = 0.f;  // replay restore (post-sync!)

    const float* A = (MODE == 0) ? g_xagg : g_hact;
    float* C = (MODE == 0) ? g_hact : Cext;
    const int aoff = (MODE == 0) ? ((ct >> 2) * 256) : 0;   // head = ct/4

    // stage A: 16 rows x K
    #pragma unroll
    for (int i = tid; i < 16 * (K / 4); i += 256) {
        int r = i / (K / 4), k4 = i % (K / 4);
        *(float4*)(As + r * ASTR + k4 * 4) =
            *(const float4*)(A + (size_t)(m0 + r) * LDA + aoff + k4 * 4);
    }
    __syncthreads();

    // compute: warp = k-group; pos = lane: r4 = lane>>3 (0..3), c8 = lane&7
    const int kg = tid >> 5;
    const int lane = tid & 31;
    const int r4 = lane >> 3, c8 = lane & 7;
    const float* Ab = As + (r4 * 4) * ASTR + kg * KQ;
    const float* Bb = Bs + kg * KQ * 32 + c8 * 4;
    float acc[4][4];
    #pragma unroll
    for (int i = 0; i < 4; i++)
        #pragma unroll
        for (int j = 0; j < 4; j++) acc[i][j] = 0.f;

    #pragma unroll 8
    for (int kk = 0; kk < KQ; kk++) {
        float4 b = *(const float4*)(Bb + kk * 32);
        float a0 = Ab[kk];
        float a1 = Ab[ASTR + kk];
        float a2 = Ab[2 * ASTR + kk];
        float a3 = Ab[3 * ASTR + kk];
        acc[0][0] += a0 * b.x; acc[0][1] += a0 * b.y; acc[0][2] += a0 * b.z; acc[0][3] += a0 * b.w;
        acc[1][0] += a1 * b.x; acc[1][1] += a1 * b.y; acc[1][2] += a1 * b.z; acc[1][3] += a1 * b.w;
        acc[2][0] += a2 * b.x; acc[2][1] += a2 * b.y; acc[2][2] += a2 * b.z; acc[2][3] += a2 * b.w;
        acc[3][0] += a3 * b.x; acc[3][1] += a3 * b.y; acc[3][2] += a3 * b.z; acc[3][3] += a3 * b.w;
    }
    __syncthreads();

    // write k-group partials into Bs alias: part[kg][16][32]
    float* part = Bs;
    #pragma unroll
    for (int i = 0; i < 4; i++)
        *(float4*)(part + kg * 512 + (r4 * 4 + i) * 32 + c8 * 4) =
            make_float4(acc[i][0], acc[i][1], acc[i][2], acc[i][3]);
    __syncthreads();

    // reduce 8 k-groups + bias + leaky + store (thread -> 2 consecutive outputs)
    {
        const int o = tid * 2;
        const int r = o >> 5, c = o & 31;
        float2 s = *(const float2*)(part + o);
        #pragma unroll
        for (int q = 1; q < 8; q++) {
            float2 t = *(const float2*)(part + q * 512 + o);
            s.x += t.x; s.y += t.y;
        }
        float2 b2 = *(const float2*)(bias + nbase + c);
        float vx = s.x + b2.x, vy = s.y + b2.y;
        vx = (vx > 0.f) ? vx : SLOPE * vx;
        vy = (vy > 0.f) ? vy : SLOPE * vy;
        *(float2*)&C[(size_t)(m0 + r) * LDC + nbase + c] = make_float2(vx, vy);
    }
}

#define GEMM0_SMEM ((16 * (256 + 4) + 256 * 32) * 4)   // 49,408 B
#define GEMM1_SMEM ((16 * (512 + 4) + 512 * 32) * 4)   // 98,560 B

// ---------------- launch ----------------
extern "C" void kernel_launch(void* const* d_in, const int* in_sizes, int n_in,
                              void* d_out, int out_size) {
    const float* x        = (const float*)d_in[0];
    const int*   ei       = (const int*)d_in[1];
    const float* ea       = (const float*)d_in[2];
    const float* W        = (const float*)d_in[5];
    const float* att_src  = (const float*)d_in[6];
    const float* att_dst  = (const float*)d_in[7];
    const float* W_edge   = (const float*)d_in[8];
    const float* att_edge = (const float*)d_in[9];
    const float* bias     = (const float*)d_in[10];
    const float* fcW      = (const float*)d_in[11];
    const float* fcb      = (const float*)d_in[12];
    float* out = (float*)d_out;
    const int E = in_sizes[1] / 2;
    const int nslab = (E + EPB - 1) / EPB;
    const float invE = 1.0f / (float)E;

    cudaFuncSetAttribute(k_gemm<0>, cudaFuncAttributeMaxDynamicSharedMemorySize, GEMM0_SMEM);
    cudaFuncSetAttribute(k_gemm<1>, cudaFuncAttributeMaxDynamicSharedMemorySize, GEMM1_SMEM);

    k_prep<<<nslab + 264, 256>>>(ei, ea, W, att_src, att_dst, W_edge, att_edge, E, nslab);

    cudaLaunchAttribute attr;
    attr.id = cudaLaunchAttributeProgrammaticStreamSerialization;
    attr.val.programmaticStreamSerializationAllowed = 1;

    {   // k_dst with PDL
        cudaLaunchConfig_t cfg = {};
        cfg.gridDim = dim3(NOUT); cfg.blockDim = dim3(256);
        cfg.dynamicSmemBytes = 0; cfg.stream = 0;
        cfg.attrs = &attr; cfg.numAttrs = 1;
        if (cudaLaunchKernelEx(&cfg, k_dst, x, ea, invE) != cudaSuccess)
            k_dst<<<NOUT, 256>>>(x, ea, invE);
    }
    {   // k_gemm<0> with PDL
        cudaLaunchConfig_t cfg = {};
        cfg.gridDim = dim3((NOUT / 16) * 16); cfg.blockDim = dim3(256);
        cfg.dynamicSmemBytes = GEMM0_SMEM; cfg.stream = 0;
        cfg.attrs = &attr; cfg.numAttrs = 1;
        if (cudaLaunchKernelEx(&cfg, k_gemm<0>, (const float*)W, (const float*)bias, (float*)nullptr) != cudaSuccess)
            k_gemm<0><<<(NOUT / 16) * 16, 256, GEMM0_SMEM>>>(W, bias, nullptr);
    }
    {   // k_gemm<1> with PDL
        cudaLaunchConfig_t cfg = {};
        cfg.gridDim = dim3((NOUT / 16) * 8); cfg.blockDim = dim3(256);
        cfg.dynamicSmemBytes = GEMM1_SMEM; cfg.stream = 0;
        cfg.attrs = &attr; cfg.numAttrs = 1;
        if (cudaLaunchKernelEx(&cfg, k_gemm<1>, (const float*)fcW, (const float*)fcb, (float*)out) != cudaSuccess)
            k_gemm<1><<<(NOUT / 16) * 8, 256, GEMM1_SMEM>>>(fcW, fcb, out);
    }
}